// round 11
// baseline (speedup 1.0000x reference)
#include <cuda_runtime.h>
#include <cuda_bf16.h>
#include <cstdint>

// Problem shape (fixed by the reference)
#define Bn 8
#define Tn 1024
#define Cn 768
#define Hn 8
#define Dn 96
#define Mn (Bn*Tn)      // 8192 rows
#define N3 (3*Cn)       // 2304
#define Kd 768

// ---------------------------------------------------------------------------
// Scratch (allocation-free rule: __device__ globals)
// ---------------------------------------------------------------------------
__device__ float g_qkv[(size_t)Mn * N3];   // [B*T, 3C]
__device__ __nv_bfloat16 g_xh[(size_t)Mn * Cn], g_xl[(size_t)Mn * Cn];
__device__ __nv_bfloat16 g_yh[(size_t)Mn * Cn], g_yl[(size_t)Mn * Cn];
__device__ __nv_bfloat16 g_WaTh[(size_t)N3 * Cn], g_WaTl[(size_t)N3 * Cn];
__device__ __nv_bfloat16 g_WpTh[(size_t)Cn * Cn], g_WpTl[(size_t)Cn * Cn];
// Attention operands: [bh][1024][96] for Q,K; [bh][96][1024] for V^T
#define AQE ((size_t)Bn * Hn * Tn * Dn)
__device__ __nv_bfloat16 g_Qh[AQE], g_Ql[AQE];
__device__ __nv_bfloat16 g_Kh[AQE], g_Kl[AQE];
__device__ __nv_bfloat16 g_VTh[AQE], g_VTl[AQE];

// ---------------------------------------------------------------------------
// Portable tensor-core primitives (sm_80+, legal at .target sm_103)
// ---------------------------------------------------------------------------
__device__ __forceinline__ uint32_t smem_u32(const void* p) {
    uint32_t a;
    asm("{ .reg .u64 t; cvta.to.shared.u64 t, %1; cvt.u32.u64 %0, t; }" : "=r"(a) : "l"(p));
    return a;
}
__device__ __forceinline__ void ldsm_x4(uint32_t* r, uint32_t addr) {
    asm volatile("ldmatrix.sync.aligned.m8n8.x4.shared.b16 {%0,%1,%2,%3}, [%4];"
                 : "=r"(r[0]), "=r"(r[1]), "=r"(r[2]), "=r"(r[3]) : "r"(addr));
}
__device__ __forceinline__ void mma_16816(float* c, const uint32_t* a, const uint32_t* b) {
    asm volatile("mma.sync.aligned.m16n8k16.row.col.f32.bf16.bf16.f32 "
                 "{%0,%1,%2,%3}, {%4,%5,%6,%7}, {%8,%9}, {%0,%1,%2,%3};"
                 : "+f"(c[0]), "+f"(c[1]), "+f"(c[2]), "+f"(c[3])
                 : "r"(a[0]), "r"(a[1]), "r"(a[2]), "r"(a[3]), "r"(b[0]), "r"(b[1]));
}
__device__ __forceinline__ void cp16(uint32_t saddr, const void* g) {
    asm volatile("cp.async.cg.shared.global [%0], [%1], 16;" :: "r"(saddr), "l"(g));
}
#define CP_COMMIT() asm volatile("cp.async.commit_group;" ::: "memory")
#define CP_WAIT0()  asm volatile("cp.async.wait_group 0;" ::: "memory")
#define CP_WAIT1()  asm volatile("cp.async.wait_group 1;" ::: "memory")

// Split a float pair into bf16x2 hi + lo words
__device__ __forceinline__ void split2w(float a, float b, uint32_t& h, uint32_t& l) {
    __nv_bfloat16 ha = __float2bfloat16(a), hb = __float2bfloat16(b);
    __nv_bfloat162 H; H.x = ha; H.y = hb;
    __nv_bfloat162 L;
    L.x = __float2bfloat16(a - __bfloat162float(ha));
    L.y = __float2bfloat16(b - __bfloat162float(hb));
    h = *(uint32_t*)&H; l = *(uint32_t*)&L;
}

// ---------------------------------------------------------------------------
// Conversion kernels
// ---------------------------------------------------------------------------
__global__ __launch_bounds__(256)
void split_fp32(const float* __restrict__ src, __nv_bfloat16* __restrict__ hi,
                __nv_bfloat16* __restrict__ lo, int n4)
{
    int i = blockIdx.x * blockDim.x + threadIdx.x;
    if (i >= n4) return;
    float4 v = ((const float4*)src)[i];
    uint32_t h0, l0, h1, l1;
    split2w(v.x, v.y, h0, l0);
    split2w(v.z, v.w, h1, l1);
    ((uint32_t*)hi)[i * 2] = h0; ((uint32_t*)hi)[i * 2 + 1] = h1;
    ((uint32_t*)lo)[i * 2] = l0; ((uint32_t*)lo)[i * 2 + 1] = l1;
}

// W[K=768, Ndim] row-major -> transposed split bf16 [Ndim, 768]
__global__ __launch_bounds__(256)
void transpose_split(const float* __restrict__ W, __nv_bfloat16* __restrict__ Th,
                     __nv_bfloat16* __restrict__ Tl, int Ndim)
{
    __shared__ float t[32][33];
    int tx = threadIdx.x & 31, ty = threadIdx.x >> 5;
    int n0 = blockIdx.x * 32, k0 = blockIdx.y * 32;
#pragma unroll
    for (int i = 0; i < 32; i += 8)
        t[ty + i][tx] = W[(size_t)(k0 + ty + i) * Ndim + n0 + tx];
    __syncthreads();
#pragma unroll
    for (int i = 0; i < 32; i += 8) {
        float v = t[tx][ty + i];
        __nv_bfloat16 h = __float2bfloat16(v);
        size_t o = (size_t)(n0 + ty + i) * Kd + k0 + tx;
        Th[o] = h;
        Tl[o] = __float2bfloat16(v - __bfloat162float(h));
    }
}

// qkv fp32 -> attention operands: Qh/Ql (pre-scaled), Kh/Kl, VTh/VTl (transposed)
__global__ __launch_bounds__(256)
void attn_prep()
{
    __shared__ float vs[128][101];
    const int tt = blockIdx.x;     // token tile 0..63 (global over 8192)
    const int h  = blockIdx.y;     // head
    const int tid = threadIdx.x;
    const int b = tt >> 3;
    const int bh = b * Hn + h;
    const int tloc = (tt & 7) * 128;
    const float* base = g_qkv + (size_t)tt * 128 * N3 + h * Dn;
    const float scale = rsqrtf((float)Dn);

    uint32_t* Qh2 = (uint32_t*)(g_Qh + ((size_t)bh * Tn + tloc) * Dn);
    uint32_t* Ql2 = (uint32_t*)(g_Ql + ((size_t)bh * Tn + tloc) * Dn);
    uint32_t* Kh2 = (uint32_t*)(g_Kh + ((size_t)bh * Tn + tloc) * Dn);
    uint32_t* Kl2 = (uint32_t*)(g_Kl + ((size_t)bh * Tn + tloc) * Dn);

    for (int i = tid; i < 128 * 24; i += 256) {
        int row = i / 24, j = i - row * 24;
        const float* p = base + (size_t)row * N3 + j * 4;
        float4 q = *(const float4*)(p);
        float4 k = *(const float4*)(p + Cn);
        float4 v = *(const float4*)(p + 2 * Cn);
        uint32_t h0, l0, h1, l1;
        split2w(q.x * scale, q.y * scale, h0, l0);
        split2w(q.z * scale, q.w * scale, h1, l1);
        int o = row * 48 + j * 2;
        Qh2[o] = h0; Qh2[o + 1] = h1; Ql2[o] = l0; Ql2[o + 1] = l1;
        split2w(k.x, k.y, h0, l0);
        split2w(k.z, k.w, h1, l1);
        Kh2[o] = h0; Kh2[o + 1] = h1; Kl2[o] = l0; Kl2[o + 1] = l1;
        vs[row][j * 4 + 0] = v.x; vs[row][j * 4 + 1] = v.y;
        vs[row][j * 4 + 2] = v.z; vs[row][j * 4 + 3] = v.w;
    }
    __syncthreads();
    for (int i = tid; i < 96 * 64; i += 256) {
        int d = i >> 6, tp = i & 63;
        uint32_t hh, ll;
        split2w(vs[2 * tp][d], vs[2 * tp + 1][d], hh, ll);
        size_t o = (((size_t)bh * Dn + d) * Tn + tloc) / 2 + tp;
        ((uint32_t*)g_VTh)[o] = hh;
        ((uint32_t*)g_VTl)[o] = ll;
    }
}

// ---------------------------------------------------------------------------
// Tensor-core GEMM via mma.sync (bf16 3-term split), 3-stage cp.async
// pipeline, BK=64, one __syncthreads per K-tile.
// 512 threads: 16 warps of 32x32 on a 128x128 tile -> 4 warps/SMSP so one
// warp's ldsm/barrier bubbles are covered by another's MMAs.
// ---------------------------------------------------------------------------
#define ROWB 144
#define TILEB (128 * ROWB)
#define STAGEB (4 * TILEB)
#define GEMM_SMEM_DYN (3 * STAGEB)  // 221184 B
#define GT 512

extern __shared__ float sm_dyn[];

__device__ __forceinline__ void gemm_issue_stage(
    const __nv_bfloat16* const* tp, uint32_t sdst, int kt, int tid)
{
#pragma unroll
    for (int i = 0; i < 8; i++) {
        int id = i * GT + tid;
        int tile = id >> 10;
        int r = (id >> 3) & 127;
        int c = id & 7;
        const __nv_bfloat16* g = tp[tile] + (size_t)r * Kd + kt * 64 + c * 8;
        cp16(sdst + tile * TILEB + r * ROWB + c * 16, g);
    }
    CP_COMMIT();
}

__global__ __launch_bounds__(GT, 1)
void tensor_gemm(const __nv_bfloat16* __restrict__ Ah, const __nv_bfloat16* __restrict__ Al,
                 const __nv_bfloat16* __restrict__ BTh, const __nv_bfloat16* __restrict__ BTl,
                 const float* __restrict__ bias, float* __restrict__ Cout, int Ndim)
{
    const int tid = threadIdx.x;
    const int wid = tid >> 5, lane = tid & 31;
    const int m0 = blockIdx.y * 128;
    const int n0 = blockIdx.x * 128;
    const int wm = (wid >> 2) * 32;        // 4 row groups of 32
    const int wn = (wid & 3) * 32;         // 4 col groups of 32

    const uint32_t sbase = smem_u32(sm_dyn);

    const __nv_bfloat16* tp[4] = {
        Ah  + (size_t)m0 * Kd, Al  + (size_t)m0 * Kd,
        BTh + (size_t)n0 * Kd, BTl + (size_t)n0 * Kd
    };

    float acc[2][4][4];
#pragma unroll
    for (int mf = 0; mf < 2; mf++)
#pragma unroll
        for (int nf = 0; nf < 4; nf++)
#pragma unroll
            for (int j = 0; j < 4; j++) acc[mf][nf][j] = 0.f;

    const int arow = wm + (lane & 15);
    const int akb  = (lane >> 4) << 3;
    const int brow = wn + (lane & 7) + ((lane >> 4) << 3);
    const int bkb  = ((lane >> 3) & 1) << 3;

    gemm_issue_stage(tp, sbase, 0, tid);
    gemm_issue_stage(tp, sbase + STAGEB, 1, tid);

    for (int kt = 0; kt < 12; kt++) {
        if (kt < 11) CP_WAIT1(); else CP_WAIT0();
        __syncthreads();

        if (kt + 2 < 12)
            gemm_issue_stage(tp, sbase + ((kt + 2) % 3) * STAGEB, kt + 2, tid);

        const uint32_t Ahb = sbase + (kt % 3) * STAGEB;
        const uint32_t Alb = Ahb + TILEB;
        const uint32_t Bhb = Ahb + 2 * TILEB;
        const uint32_t Blb = Ahb + 3 * TILEB;

#pragma unroll
        for (int kf = 0; kf < 4; kf++) {
            const int kb = kf * 16;
            uint32_t ah[2][4], al[2][4], bh[4][2], bl[4][2];
#pragma unroll
            for (int mf = 0; mf < 2; mf++) {
                uint32_t off = (uint32_t)(arow + mf * 16) * ROWB + (kb + akb) * 2;
                ldsm_x4(ah[mf], Ahb + off);
                ldsm_x4(al[mf], Alb + off);
            }
#pragma unroll
            for (int np = 0; np < 2; np++) {
                uint32_t off = (uint32_t)(brow + np * 16) * ROWB + (kb + bkb) * 2;
                uint32_t t4[4];
                ldsm_x4(t4, Bhb + off);
                bh[2 * np][0] = t4[0]; bh[2 * np][1] = t4[1];
                bh[2 * np + 1][0] = t4[2]; bh[2 * np + 1][1] = t4[3];
                ldsm_x4(t4, Blb + off);
                bl[2 * np][0] = t4[0]; bl[2 * np][1] = t4[1];
                bl[2 * np + 1][0] = t4[2]; bl[2 * np + 1][1] = t4[3];
            }
#pragma unroll
            for (int mf = 0; mf < 2; mf++)
#pragma unroll
                for (int nf = 0; nf < 4; nf++)
                    mma_16816(acc[mf][nf], ah[mf], bh[nf]);
#pragma unroll
            for (int mf = 0; mf < 2; mf++)
#pragma unroll
                for (int nf = 0; nf < 4; nf++)
                    mma_16816(acc[mf][nf], ah[mf], bl[nf]);
#pragma unroll
            for (int mf = 0; mf < 2; mf++)
#pragma unroll
                for (int nf = 0; nf < 4; nf++)
                    mma_16816(acc[mf][nf], al[mf], bh[nf]);
        }
    }

    const int mrow = m0 + wm + (lane >> 2);
    const int ncol = n0 + wn + (lane & 3) * 2;
#pragma unroll
    for (int mf = 0; mf < 2; mf++)
#pragma unroll
        for (int nf = 0; nf < 4; nf++) {
            int r = mrow + mf * 16, c = ncol + nf * 8;
            float b0 = bias[c], b1 = bias[c + 1];
            *(float2*)(Cout + (size_t)r * Ndim + c) =
                make_float2(acc[mf][nf][0] + b0, acc[mf][nf][1] + b1);
            *(float2*)(Cout + (size_t)(r + 8) * Ndim + c) =
                make_float2(acc[mf][nf][2] + b0, acc[mf][nf][3] + b1);
        }
}

// ---------------------------------------------------------------------------
// Tensor-core flash attention (unchanged from R10 passing kernel).
// K double-buffered, V staggered; qt reversed.
// ---------------------------------------------------------------------------
#define SQp 208
#define SVp 272
#define AOFF_QH 0
#define AOFF_QL (128 * SQp)
#define AOFF_K  (2 * 128 * SQp)
#define KSTGB   (2 * 128 * SQp)
#define AOFF_VH (AOFF_K + 2 * KSTGB)
#define AOFF_VL (AOFF_VH + 96 * SVp)
#define ATT_SMEM (AOFF_VL + 96 * SVp)   // 211968 B

__device__ __forceinline__ void att_load_K(uint32_t kbase, const __nv_bfloat16* kh,
                                           const __nv_bfloat16* kl, int tid)
{
    for (int i = tid; i < 128 * 12; i += 256) {
        int r = i / 12, c = i - r * 12;
        cp16(kbase + r * SQp + c * 16, kh + r * Dn + c * 8);
        cp16(kbase + 128 * SQp + r * SQp + c * 16, kl + r * Dn + c * 8);
    }
    CP_COMMIT();
}
__device__ __forceinline__ void att_load_V(uint32_t sb, const __nv_bfloat16* gVh,
                                           const __nv_bfloat16* gVl, int kt, int tid)
{
    for (int i = tid; i < 96 * 16; i += 256) {
        int d = i >> 4, c = i & 15;
        cp16(sb + AOFF_VH + d * SVp + c * 16, gVh + (size_t)d * Tn + kt * 128 + c * 8);
        cp16(sb + AOFF_VL + d * SVp + c * 16, gVl + (size_t)d * Tn + kt * 128 + c * 8);
    }
    CP_COMMIT();
}

__global__ __launch_bounds__(256, 1)
void attention_mma()
{
    const int tid = threadIdx.x, lane = tid & 31, w = tid >> 5;
    const int qt = gridDim.x - 1 - blockIdx.x;   // long CTAs first
    const int bh = blockIdx.y;
    const int b = bh >> 3, h = bh & 7;
    const uint32_t sb = smem_u32(sm_dyn);

    const __nv_bfloat16* gQh = g_Qh + ((size_t)bh * Tn + qt * 128) * Dn;
    const __nv_bfloat16* gQl = g_Ql + ((size_t)bh * Tn + qt * 128) * Dn;
    const __nv_bfloat16* gKh = g_Kh + (size_t)bh * Tn * Dn;
    const __nv_bfloat16* gKl = g_Kl + (size_t)bh * Tn * Dn;
    const __nv_bfloat16* gVh = g_VTh + (size_t)bh * Dn * Tn;
    const __nv_bfloat16* gVl = g_VTl + (size_t)bh * Dn * Tn;

    for (int i = tid; i < 128 * 12; i += 256) {
        int r = i / 12, c = i - r * 12;
        cp16(sb + AOFF_QH + r * SQp + c * 16, gQh + r * Dn + c * 8);
        cp16(sb + AOFF_QL + r * SQp + c * 16, gQl + r * Dn + c * 8);
        cp16(sb + AOFF_K + r * SQp + c * 16, gKh + r * Dn + c * 8);
        cp16(sb + AOFF_K + 128 * SQp + r * SQp + c * 16, gKl + r * Dn + c * 8);
    }
    CP_COMMIT();
    att_load_V(sb, gVh, gVl, 0, tid);

    float oacc[12][4];
#pragma unroll
    for (int i = 0; i < 12; i++)
#pragma unroll
        for (int j = 0; j < 4; j++) oacc[i][j] = 0.f;
    float m0 = -1e30f, m1 = -1e30f, l0 = 0.f, l1 = 0.f;

    for (int kt = 0; kt <= qt; kt++) {
        CP_WAIT1();
        __syncthreads();

        if (kt < qt)
            att_load_K(sb + AOFF_K + ((kt + 1) & 1) * KSTGB,
                       gKh + (size_t)(kt + 1) * 128 * Dn,
                       gKl + (size_t)(kt + 1) * 128 * Dn, tid);

        const uint32_t Khb = sb + AOFF_K + (kt & 1) * KSTGB;
        const uint32_t Klb = Khb + 128 * SQp;

        float sacc[16][4];
#pragma unroll
        for (int i = 0; i < 16; i++)
#pragma unroll
            for (int j = 0; j < 4; j++) sacc[i][j] = 0.f;

#pragma unroll
        for (int kf = 0; kf < 6; kf++) {
            uint32_t qoff = (uint32_t)(w * 16 + (lane & 15)) * SQp + kf * 32 + (lane >> 4) * 16;
            uint32_t ah[4], al[4];
            ldsm_x4(ah, sb + AOFF_QH + qoff);
            ldsm_x4(al, sb + AOFF_QL + qoff);
#pragma unroll
            for (int p = 0; p < 8; p++) {
                uint32_t koff = (uint32_t)(p * 16 + (lane & 15)) * SQp + kf * 32 + (lane >> 4) * 16;
                uint32_t kh4[4], kl4[4];
                ldsm_x4(kh4, Khb + koff);
                ldsm_x4(kl4, Klb + koff);
                uint32_t b0h[2] = {kh4[0], kh4[2]}, b1h[2] = {kh4[1], kh4[3]};
                uint32_t b0l[2] = {kl4[0], kl4[2]}, b1l[2] = {kl4[1], kl4[3]};
                mma_16816(sacc[2 * p],     ah, b0h);
                mma_16816(sacc[2 * p + 1], ah, b1h);
                mma_16816(sacc[2 * p],     ah, b0l);
                mma_16816(sacc[2 * p + 1], ah, b1l);
                mma_16816(sacc[2 * p],     al, b0h);
                mma_16816(sacc[2 * p + 1], al, b1h);
            }
        }

        if (kt == qt) {
            const int lr0 = w * 16 + (lane >> 2), lr1 = lr0 + 8;
#pragma unroll
            for (int nf = 0; nf < 16; nf++) {
                int lc = nf * 8 + (lane & 3) * 2;
                if (lc     > lr0) sacc[nf][0] = -1e30f;
                if (lc + 1 > lr0) sacc[nf][1] = -1e30f;
                if (lc     > lr1) sacc[nf][2] = -1e30f;
                if (lc + 1 > lr1) sacc[nf][3] = -1e30f;
            }
        }

        float tm0 = -1e30f, tm1 = -1e30f;
#pragma unroll
        for (int nf = 0; nf < 16; nf++) {
            tm0 = fmaxf(tm0, fmaxf(sacc[nf][0], sacc[nf][1]));
            tm1 = fmaxf(tm1, fmaxf(sacc[nf][2], sacc[nf][3]));
        }
        tm0 = fmaxf(tm0, __shfl_xor_sync(0xffffffffu, tm0, 1));
        tm0 = fmaxf(tm0, __shfl_xor_sync(0xffffffffu, tm0, 2));
        tm1 = fmaxf(tm1, __shfl_xor_sync(0xffffffffu, tm1, 1));
        tm1 = fmaxf(tm1, __shfl_xor_sync(0xffffffffu, tm1, 2));
        float nm0 = fmaxf(m0, tm0), nm1 = fmaxf(m1, tm1);
        float c0 = __expf(m0 - nm0), c1 = __expf(m1 - nm1);
        m0 = nm0; m1 = nm1;
        float ts0 = 0.f, ts1 = 0.f;
#pragma unroll
        for (int nf = 0; nf < 16; nf++) {
            sacc[nf][0] = __expf(sacc[nf][0] - nm0);
            sacc[nf][1] = __expf(sacc[nf][1] - nm0);
            sacc[nf][2] = __expf(sacc[nf][2] - nm1);
            sacc[nf][3] = __expf(sacc[nf][3] - nm1);
            ts0 += sacc[nf][0] + sacc[nf][1];
            ts1 += sacc[nf][2] + sacc[nf][3];
        }
        ts0 += __shfl_xor_sync(0xffffffffu, ts0, 1);
        ts0 += __shfl_xor_sync(0xffffffffu, ts0, 2);
        ts1 += __shfl_xor_sync(0xffffffffu, ts1, 1);
        ts1 += __shfl_xor_sync(0xffffffffu, ts1, 2);
        l0 = l0 * c0 + ts0;
        l1 = l1 * c1 + ts1;
#pragma unroll
        for (int nf = 0; nf < 12; nf++) {
            oacc[nf][0] *= c0; oacc[nf][1] *= c0;
            oacc[nf][2] *= c1; oacc[nf][3] *= c1;
        }

        if (kt < qt) CP_WAIT1(); else CP_WAIT0();
        __syncthreads();

#pragma unroll
        for (int t = 0; t < 8; t++) {
            uint32_t pah[4], pal[4];
            split2w(sacc[2 * t][0],     sacc[2 * t][1],     pah[0], pal[0]);
            split2w(sacc[2 * t][2],     sacc[2 * t][3],     pah[1], pal[1]);
            split2w(sacc[2 * t + 1][0], sacc[2 * t + 1][1], pah[2], pal[2]);
            split2w(sacc[2 * t + 1][2], sacc[2 * t + 1][3], pah[3], pal[3]);
#pragma unroll
            for (int dp = 0; dp < 6; dp++) {
                uint32_t voff = (uint32_t)(dp * 16 + (lane & 15)) * SVp + t * 32 + (lane >> 4) * 16;
                uint32_t vh4[4], vl4[4];
                ldsm_x4(vh4, sb + AOFF_VH + voff);
                ldsm_x4(vl4, sb + AOFF_VL + voff);
                uint32_t b0h[2] = {vh4[0], vh4[2]}, b1h[2] = {vh4[1], vh4[3]};
                uint32_t b0l[2] = {vl4[0], vl4[2]}, b1l[2] = {vl4[1], vl4[3]};
                mma_16816(oacc[2 * dp],     pah, b0h);
                mma_16816(oacc[2 * dp + 1], pah, b1h);
                mma_16816(oacc[2 * dp],     pah, b0l);
                mma_16816(oacc[2 * dp + 1], pah, b1l);
                mma_16816(oacc[2 * dp],     pal, b0h);
                mma_16816(oacc[2 * dp + 1], pal, b1h);
            }
        }

        __syncthreads();
        if (kt < qt)
            att_load_V(sb, gVh, gVl, kt + 1, tid);
    }

    const float i0 = 1.f / l0, i1 = 1.f / l1;
    const size_t row0 = (size_t)b * Tn + qt * 128 + w * 16 + (lane >> 2);
#pragma unroll
    for (int nf = 0; nf < 12; nf++) {
        int col = h * Dn + nf * 8 + (lane & 3) * 2;
        uint32_t hh, ll;
        split2w(oacc[nf][0] * i0, oacc[nf][1] * i0, hh, ll);
        *(uint32_t*)(g_yh + row0 * Cn + col) = hh;
        *(uint32_t*)(g_yl + row0 * Cn + col) = ll;
        split2w(oacc[nf][2] * i1, oacc[nf][3] * i1, hh, ll);
        *(uint32_t*)(g_yh + (row0 + 8) * Cn + col) = hh;
        *(uint32_t*)(g_yl + (row0 + 8) * Cn + col) = ll;
    }
}

// ---------------------------------------------------------------------------
// Launch pipeline
// ---------------------------------------------------------------------------
extern "C" void kernel_launch(void* const* d_in, const int* in_sizes, int n_in,
                              void* d_out, int out_size)
{
    const float* x      = (const float*)d_in[0];
    const float* W_attn = (const float*)d_in[1];
    const float* b_attn = (const float*)d_in[2];
    const float* W_proj = (const float*)d_in[3];
    const float* b_proj = (const float*)d_in[4];
    float* out = (float*)d_out;

    float* qkv;
    __nv_bfloat16 *xh, *xl, *yh, *yl, *wath, *watl, *wpth, *wptl;
    cudaGetSymbolAddress((void**)&qkv,  g_qkv);
    cudaGetSymbolAddress((void**)&xh,   g_xh);
    cudaGetSymbolAddress((void**)&xl,   g_xl);
    cudaGetSymbolAddress((void**)&yh,   g_yh);
    cudaGetSymbolAddress((void**)&yl,   g_yl);
    cudaGetSymbolAddress((void**)&wath, g_WaTh);
    cudaGetSymbolAddress((void**)&watl, g_WaTl);
    cudaGetSymbolAddress((void**)&wpth, g_WpTh);
    cudaGetSymbolAddress((void**)&wptl, g_WpTl);

    cudaFuncSetAttribute(tensor_gemm,
                         cudaFuncAttributeMaxDynamicSharedMemorySize, GEMM_SMEM_DYN);
    cudaFuncSetAttribute(attention_mma,
                         cudaFuncAttributeMaxDynamicSharedMemorySize, ATT_SMEM);

    const int n4x = (Mn * Cn) / 4;
    split_fp32<<<(n4x + 255) / 256, 256>>>(x, xh, xl, n4x);
    transpose_split<<<dim3(N3 / 32, Kd / 32), 256>>>(W_attn, wath, watl, N3);
    transpose_split<<<dim3(Cn / 32, Kd / 32), 256>>>(W_proj, wpth, wptl, Cn);

    // 1) qkv = x @ W_attn + b_attn   [8192, 2304]
    tensor_gemm<<<dim3(N3 / 128, Mn / 128), GT, GEMM_SMEM_DYN>>>(
        xh, xl, wath, watl, b_attn, qkv, N3);

    // 2) attention operand prep + pipelined flash attention
    attn_prep<<<dim3(Mn / 128, Hn), 256>>>();
    attention_mma<<<dim3(Tn / 128, Bn * Hn), 256, ATT_SMEM>>>();

    // 3) out = y @ W_proj + b_proj   [8192, 768]
    tensor_gemm<<<dim3(Cn / 128, Mn / 128), GT, GEMM_SMEM_DYN>>>(
        yh, yl, wpth, wptl, b_proj, out, Cn);
}

// round 12
// speedup vs baseline: 2.0978x; 2.0978x over previous
#include <cuda_runtime.h>
#include <cuda_fp16.h>
#include <cstdint>

// Problem shape (fixed by the reference)
#define Bn 8
#define Tn 1024
#define Cn 768
#define Hn 8
#define Dn 96
#define Mn (Bn*Tn)      // 8192 rows
#define N3 (3*Cn)       // 2304
#define Kd 768

// ---------------------------------------------------------------------------
// Scratch (allocation-free rule: __device__ globals)
// ---------------------------------------------------------------------------
__device__ float g_qkv[(size_t)Mn * N3];   // [B*T, 3C] fp32
__device__ __half g_x16[(size_t)Mn * Cn];
__device__ __half g_y16[(size_t)Mn * Cn];
__device__ __half g_WaT[(size_t)N3 * Cn];  // W_attn^T [2304,768]
__device__ __half g_WpT[(size_t)Cn * Cn];  // W_proj^T [768,768]
// Attention operands: [bh][1024][96] for Q,K; [bh][96][1024] for V^T
#define AQE ((size_t)Bn * Hn * Tn * Dn)
__device__ __half g_Q16[AQE], g_K16[AQE], g_VT16[AQE];

// ---------------------------------------------------------------------------
// Portable tensor-core primitives (sm_80+, legal at .target sm_103)
// ---------------------------------------------------------------------------
__device__ __forceinline__ uint32_t smem_u32(const void* p) {
    uint32_t a;
    asm("{ .reg .u64 t; cvta.to.shared.u64 t, %1; cvt.u32.u64 %0, t; }" : "=r"(a) : "l"(p));
    return a;
}
__device__ __forceinline__ void ldsm_x4(uint32_t* r, uint32_t addr) {
    asm volatile("ldmatrix.sync.aligned.m8n8.x4.shared.b16 {%0,%1,%2,%3}, [%4];"
                 : "=r"(r[0]), "=r"(r[1]), "=r"(r[2]), "=r"(r[3]) : "r"(addr));
}
__device__ __forceinline__ void mma_16816(float* c, const uint32_t* a, const uint32_t* b) {
    asm volatile("mma.sync.aligned.m16n8k16.row.col.f32.f16.f16.f32 "
                 "{%0,%1,%2,%3}, {%4,%5,%6,%7}, {%8,%9}, {%0,%1,%2,%3};"
                 : "+f"(c[0]), "+f"(c[1]), "+f"(c[2]), "+f"(c[3])
                 : "r"(a[0]), "r"(a[1]), "r"(a[2]), "r"(a[3]), "r"(b[0]), "r"(b[1]));
}
__device__ __forceinline__ void cp16(uint32_t saddr, const void* g) {
    asm volatile("cp.async.cg.shared.global [%0], [%1], 16;" :: "r"(saddr), "l"(g));
}
#define CP_COMMIT() asm volatile("cp.async.commit_group;" ::: "memory")
#define CP_WAIT0()  asm volatile("cp.async.wait_group 0;" ::: "memory")
#define CP_WAIT1()  asm volatile("cp.async.wait_group 1;" ::: "memory")

__device__ __forceinline__ uint32_t pack2h(float a, float b) {
    __half2 p = __floats2half2_rn(a, b);
    return *(uint32_t*)&p;
}

// ---------------------------------------------------------------------------
// Conversion kernels
// ---------------------------------------------------------------------------
__global__ __launch_bounds__(256)
void cvt_fp16(const float* __restrict__ src, __half* __restrict__ dst, int n4)
{
    int i = blockIdx.x * blockDim.x + threadIdx.x;
    if (i >= n4) return;
    float4 v = ((const float4*)src)[i];
    ((uint32_t*)dst)[i * 2]     = pack2h(v.x, v.y);
    ((uint32_t*)dst)[i * 2 + 1] = pack2h(v.z, v.w);
}

// W[K=768, Ndim] row-major -> transposed fp16 [Ndim, 768]
__global__ __launch_bounds__(256)
void transpose_cvt(const float* __restrict__ W, __half* __restrict__ T, int Ndim)
{
    __shared__ float t[32][33];
    int tx = threadIdx.x & 31, ty = threadIdx.x >> 5;
    int n0 = blockIdx.x * 32, k0 = blockIdx.y * 32;
#pragma unroll
    for (int i = 0; i < 32; i += 8)
        t[ty + i][tx] = W[(size_t)(k0 + ty + i) * Ndim + n0 + tx];
    __syncthreads();
#pragma unroll
    for (int i = 0; i < 32; i += 8)
        T[(size_t)(n0 + ty + i) * Kd + k0 + tx] = __float2half_rn(t[tx][ty + i]);
}

// qkv fp32 -> attention operands: Q16 (pre-scaled), K16, VT16 (transposed)
__global__ __launch_bounds__(256)
void attn_prep()
{
    __shared__ float vs[128][101];
    const int tt = blockIdx.x;     // token tile 0..63 (global over 8192)
    const int h  = blockIdx.y;     // head
    const int tid = threadIdx.x;
    const int b = tt >> 3;
    const int bh = b * Hn + h;
    const int tloc = (tt & 7) * 128;
    const float* base = g_qkv + (size_t)tt * 128 * N3 + h * Dn;
    const float scale = rsqrtf((float)Dn);

    uint32_t* Q2 = (uint32_t*)(g_Q16 + ((size_t)bh * Tn + tloc) * Dn);
    uint32_t* K2 = (uint32_t*)(g_K16 + ((size_t)bh * Tn + tloc) * Dn);

    for (int i = tid; i < 128 * 24; i += 256) {
        int row = i / 24, j = i - row * 24;
        const float* p = base + (size_t)row * N3 + j * 4;
        float4 q = *(const float4*)(p);
        float4 k = *(const float4*)(p + Cn);
        float4 v = *(const float4*)(p + 2 * Cn);
        int o = row * 48 + j * 2;
        Q2[o]     = pack2h(q.x * scale, q.y * scale);
        Q2[o + 1] = pack2h(q.z * scale, q.w * scale);
        K2[o]     = pack2h(k.x, k.y);
        K2[o + 1] = pack2h(k.z, k.w);
        vs[row][j * 4 + 0] = v.x; vs[row][j * 4 + 1] = v.y;
        vs[row][j * 4 + 2] = v.z; vs[row][j * 4 + 3] = v.w;
    }
    __syncthreads();
    for (int i = tid; i < 96 * 64; i += 256) {
        int d = i >> 6, tp = i & 63;
        size_t o = (((size_t)bh * Dn + d) * Tn + tloc) / 2 + tp;
        ((uint32_t*)g_VT16)[o] = pack2h(vs[2 * tp][d], vs[2 * tp + 1][d]);
    }
}

// ---------------------------------------------------------------------------
// Tensor-core GEMM via mma.sync, fp16 single-term, fp32 accumulate.
// 3-stage cp.async pipeline, BK=64, one __syncthreads per K-tile.
// 256 threads, 8 warps of 64x32 on a 128x128 tile (best-known R9 geometry).
// Smem rows 144B (9x16B): chunk index 9r mod 8 is a permutation ->
// conflict-free ldmatrix.
// ---------------------------------------------------------------------------
#define ROWB 144
#define TILEB (128 * ROWB)          // 18432 B per 128x64-fp16 tile
#define STAGEB (2 * TILEB)          // A | B = 36864 B
#define GEMM_SMEM_DYN (3 * STAGEB)  // 110592 B

extern __shared__ float sm_dyn[];

__device__ __forceinline__ void gemm_issue_stage(
    const __half* const* tp, uint32_t sdst, int kt, int tid)
{
#pragma unroll
    for (int i = 0; i < 8; i++) {
        int id = i * 256 + tid;
        int tile = id >> 10;
        int r = (id >> 3) & 127;
        int c = id & 7;
        const __half* g = tp[tile] + (size_t)r * Kd + kt * 64 + c * 8;
        cp16(sdst + tile * TILEB + r * ROWB + c * 16, g);
    }
    CP_COMMIT();
}

__global__ __launch_bounds__(256, 1)
void tensor_gemm(const __half* __restrict__ A, const __half* __restrict__ BT,
                 const float* __restrict__ bias, float* __restrict__ Cout, int Ndim)
{
    const int tid = threadIdx.x;
    const int wid = tid >> 5, lane = tid & 31;
    const int m0 = blockIdx.y * 128;
    const int n0 = blockIdx.x * 128;
    const int wm = (wid >> 2) * 64;
    const int wn = (wid & 3) * 32;

    const uint32_t sbase = smem_u32(sm_dyn);

    const __half* tp[2] = { A + (size_t)m0 * Kd, BT + (size_t)n0 * Kd };

    float acc[4][4][4];
#pragma unroll
    for (int mf = 0; mf < 4; mf++)
#pragma unroll
        for (int nf = 0; nf < 4; nf++)
#pragma unroll
            for (int j = 0; j < 4; j++) acc[mf][nf][j] = 0.f;

    const int arow = wm + (lane & 15);
    const int akb  = (lane >> 4) << 3;
    const int brow = wn + (lane & 7) + ((lane >> 4) << 3);
    const int bkb  = ((lane >> 3) & 1) << 3;

    gemm_issue_stage(tp, sbase, 0, tid);
    gemm_issue_stage(tp, sbase + STAGEB, 1, tid);

    for (int kt = 0; kt < 12; kt++) {
        if (kt < 11) CP_WAIT1(); else CP_WAIT0();
        __syncthreads();

        if (kt + 2 < 12)
            gemm_issue_stage(tp, sbase + ((kt + 2) % 3) * STAGEB, kt + 2, tid);

        const uint32_t Ab = sbase + (kt % 3) * STAGEB;
        const uint32_t Bb = Ab + TILEB;

#pragma unroll
        for (int kf = 0; kf < 4; kf++) {
            const int kb = kf * 16;
            uint32_t a4[4][4], b4[4][2];
#pragma unroll
            for (int mf = 0; mf < 4; mf++)
                ldsm_x4(a4[mf], Ab + (uint32_t)(arow + mf * 16) * ROWB + (kb + akb) * 2);
#pragma unroll
            for (int np = 0; np < 2; np++) {
                uint32_t t4[4];
                ldsm_x4(t4, Bb + (uint32_t)(brow + np * 16) * ROWB + (kb + bkb) * 2);
                b4[2 * np][0] = t4[0]; b4[2 * np][1] = t4[1];
                b4[2 * np + 1][0] = t4[2]; b4[2 * np + 1][1] = t4[3];
            }
#pragma unroll
            for (int mf = 0; mf < 4; mf++)
#pragma unroll
                for (int nf = 0; nf < 4; nf++)
                    mma_16816(acc[mf][nf], a4[mf], b4[nf]);
        }
    }

    const int mrow = m0 + wm + (lane >> 2);
    const int ncol = n0 + wn + (lane & 3) * 2;
#pragma unroll
    for (int mf = 0; mf < 4; mf++)
#pragma unroll
        for (int nf = 0; nf < 4; nf++) {
            int r = mrow + mf * 16, c = ncol + nf * 8;
            float b0 = bias[c], b1 = bias[c + 1];
            *(float2*)(Cout + (size_t)r * Ndim + c) =
                make_float2(acc[mf][nf][0] + b0, acc[mf][nf][1] + b1);
            *(float2*)(Cout + (size_t)(r + 8) * Ndim + c) =
                make_float2(acc[mf][nf][2] + b0, acc[mf][nf][3] + b1);
        }
}

// ---------------------------------------------------------------------------
// Tensor-core flash attention, fp16 single-term.
// K double-buffered, V staggered; qt reversed (long CTAs first).
// smem: Q 26624 + K 2x26624 + V 26112 = 105984 B
// ---------------------------------------------------------------------------
#define SQp 208
#define SVp 272
#define AOFF_Q 0
#define AOFF_K (128 * SQp)
#define KSTGB  (128 * SQp)
#define AOFF_V (AOFF_K + 2 * KSTGB)
#define ATT_SMEM (AOFF_V + 96 * SVp)   // 105984 B

__device__ __forceinline__ void att_load_K(uint32_t kbase, const __half* kh, int tid)
{
    for (int i = tid; i < 128 * 12; i += 256) {
        int r = i / 12, c = i - r * 12;
        cp16(kbase + r * SQp + c * 16, kh + r * Dn + c * 8);
    }
    CP_COMMIT();
}
__device__ __forceinline__ void att_load_V(uint32_t sb, const __half* gV, int kt, int tid)
{
    for (int i = tid; i < 96 * 16; i += 256) {
        int d = i >> 4, c = i & 15;
        cp16(sb + AOFF_V + d * SVp + c * 16, gV + (size_t)d * Tn + kt * 128 + c * 8);
    }
    CP_COMMIT();
}

__global__ __launch_bounds__(256, 1)
void attention_mma()
{
    const int tid = threadIdx.x, lane = tid & 31, w = tid >> 5;
    const int qt = gridDim.x - 1 - blockIdx.x;   // long CTAs first
    const int bh = blockIdx.y;
    const int b = bh >> 3, h = bh & 7;
    const uint32_t sb = smem_u32(sm_dyn);

    const __half* gQ = g_Q16 + ((size_t)bh * Tn + qt * 128) * Dn;
    const __half* gK = g_K16 + (size_t)bh * Tn * Dn;
    const __half* gV = g_VT16 + (size_t)bh * Dn * Tn;

    // Preamble: Q + K0 as one group, V0 as second group
    for (int i = tid; i < 128 * 12; i += 256) {
        int r = i / 12, c = i - r * 12;
        cp16(sb + AOFF_Q + r * SQp + c * 16, gQ + r * Dn + c * 8);
        cp16(sb + AOFF_K + r * SQp + c * 16, gK + r * Dn + c * 8);
    }
    CP_COMMIT();
    att_load_V(sb, gV, 0, tid);

    float oacc[12][4];
#pragma unroll
    for (int i = 0; i < 12; i++)
#pragma unroll
        for (int j = 0; j < 4; j++) oacc[i][j] = 0.f;
    float m0 = -1e30f, m1 = -1e30f, l0 = 0.f, l1 = 0.f;

    for (int kt = 0; kt <= qt; kt++) {
        CP_WAIT1();
        __syncthreads();

        if (kt < qt)
            att_load_K(sb + AOFF_K + ((kt + 1) & 1) * KSTGB,
                       gK + (size_t)(kt + 1) * 128 * Dn, tid);

        const uint32_t Kb = sb + AOFF_K + (kt & 1) * KSTGB;

        // ---- S = Q K^T ----
        float sacc[16][4];
#pragma unroll
        for (int i = 0; i < 16; i++)
#pragma unroll
            for (int j = 0; j < 4; j++) sacc[i][j] = 0.f;

#pragma unroll
        for (int kf = 0; kf < 6; kf++) {
            uint32_t qoff = (uint32_t)(w * 16 + (lane & 15)) * SQp + kf * 32 + (lane >> 4) * 16;
            uint32_t a4[4];
            ldsm_x4(a4, sb + AOFF_Q + qoff);
#pragma unroll
            for (int p = 0; p < 8; p++) {
                uint32_t k4[4];
                ldsm_x4(k4, Kb + (uint32_t)(p * 16 + (lane & 15)) * SQp + kf * 32 + (lane >> 4) * 16);
                uint32_t b0[2] = {k4[0], k4[2]}, b1[2] = {k4[1], k4[3]};
                mma_16816(sacc[2 * p],     a4, b0);
                mma_16816(sacc[2 * p + 1], a4, b1);
            }
        }

        if (kt == qt) {
            const int lr0 = w * 16 + (lane >> 2), lr1 = lr0 + 8;
#pragma unroll
            for (int nf = 0; nf < 16; nf++) {
                int lc = nf * 8 + (lane & 3) * 2;
                if (lc     > lr0) sacc[nf][0] = -1e30f;
                if (lc + 1 > lr0) sacc[nf][1] = -1e30f;
                if (lc     > lr1) sacc[nf][2] = -1e30f;
                if (lc + 1 > lr1) sacc[nf][3] = -1e30f;
            }
        }

        // ---- online softmax ----
        float tm0 = -1e30f, tm1 = -1e30f;
#pragma unroll
        for (int nf = 0; nf < 16; nf++) {
            tm0 = fmaxf(tm0, fmaxf(sacc[nf][0], sacc[nf][1]));
            tm1 = fmaxf(tm1, fmaxf(sacc[nf][2], sacc[nf][3]));
        }
        tm0 = fmaxf(tm0, __shfl_xor_sync(0xffffffffu, tm0, 1));
        tm0 = fmaxf(tm0, __shfl_xor_sync(0xffffffffu, tm0, 2));
        tm1 = fmaxf(tm1, __shfl_xor_sync(0xffffffffu, tm1, 1));
        tm1 = fmaxf(tm1, __shfl_xor_sync(0xffffffffu, tm1, 2));
        float nm0 = fmaxf(m0, tm0), nm1 = fmaxf(m1, tm1);
        float c0 = __expf(m0 - nm0), c1 = __expf(m1 - nm1);
        m0 = nm0; m1 = nm1;
        float ts0 = 0.f, ts1 = 0.f;
#pragma unroll
        for (int nf = 0; nf < 16; nf++) {
            sacc[nf][0] = __expf(sacc[nf][0] - nm0);
            sacc[nf][1] = __expf(sacc[nf][1] - nm0);
            sacc[nf][2] = __expf(sacc[nf][2] - nm1);
            sacc[nf][3] = __expf(sacc[nf][3] - nm1);
            ts0 += sacc[nf][0] + sacc[nf][1];
            ts1 += sacc[nf][2] + sacc[nf][3];
        }
        ts0 += __shfl_xor_sync(0xffffffffu, ts0, 1);
        ts0 += __shfl_xor_sync(0xffffffffu, ts0, 2);
        ts1 += __shfl_xor_sync(0xffffffffu, ts1, 1);
        ts1 += __shfl_xor_sync(0xffffffffu, ts1, 2);
        l0 = l0 * c0 + ts0;
        l1 = l1 * c1 + ts1;
#pragma unroll
        for (int nf = 0; nf < 12; nf++) {
            oacc[nf][0] *= c0; oacc[nf][1] *= c0;
            oacc[nf][2] *= c1; oacc[nf][3] *= c1;
        }

        // wait V(kt): only K(kt+1) may remain in flight
        if (kt < qt) CP_WAIT1(); else CP_WAIT0();
        __syncthreads();

        // ---- O += P V (P packed fp16 from S accumulators) ----
#pragma unroll
        for (int t = 0; t < 8; t++) {
            uint32_t pa[4];
            pa[0] = pack2h(sacc[2 * t][0],     sacc[2 * t][1]);
            pa[1] = pack2h(sacc[2 * t][2],     sacc[2 * t][3]);
            pa[2] = pack2h(sacc[2 * t + 1][0], sacc[2 * t + 1][1]);
            pa[3] = pack2h(sacc[2 * t + 1][2], sacc[2 * t + 1][3]);
#pragma unroll
            for (int dp = 0; dp < 6; dp++) {
                uint32_t v4[4];
                ldsm_x4(v4, sb + AOFF_V + (uint32_t)(dp * 16 + (lane & 15)) * SVp
                               + t * 32 + (lane >> 4) * 16);
                uint32_t b0[2] = {v4[0], v4[2]}, b1[2] = {v4[1], v4[3]};
                mma_16816(oacc[2 * dp],     pa, b0);
                mma_16816(oacc[2 * dp + 1], pa, b1);
            }
        }

        // all warps done reading V(kt) -> safe to overwrite
        __syncthreads();
        if (kt < qt)
            att_load_V(sb, gV, kt + 1, tid);
    }

    // ---- epilogue: normalize, write y fp16 [B*T, C] ----
    const float i0 = 1.f / l0, i1 = 1.f / l1;
    const size_t row0 = (size_t)b * Tn + qt * 128 + w * 16 + (lane >> 2);
#pragma unroll
    for (int nf = 0; nf < 12; nf++) {
        int col = h * Dn + nf * 8 + (lane & 3) * 2;
        *(uint32_t*)(g_y16 + row0 * Cn + col) =
            pack2h(oacc[nf][0] * i0, oacc[nf][1] * i0);
        *(uint32_t*)(g_y16 + (row0 + 8) * Cn + col) =
            pack2h(oacc[nf][2] * i1, oacc[nf][3] * i1);
    }
}

// ---------------------------------------------------------------------------
// Launch pipeline
// ---------------------------------------------------------------------------
extern "C" void kernel_launch(void* const* d_in, const int* in_sizes, int n_in,
                              void* d_out, int out_size)
{
    const float* x      = (const float*)d_in[0];
    const float* W_attn = (const float*)d_in[1];
    const float* b_attn = (const float*)d_in[2];
    const float* W_proj = (const float*)d_in[3];
    const float* b_proj = (const float*)d_in[4];
    float* out = (float*)d_out;

    float* qkv;
    __half *x16, *y16, *wat, *wpt;
    cudaGetSymbolAddress((void**)&qkv, g_qkv);
    cudaGetSymbolAddress((void**)&x16, g_x16);
    cudaGetSymbolAddress((void**)&y16, g_y16);
    cudaGetSymbolAddress((void**)&wat, g_WaT);
    cudaGetSymbolAddress((void**)&wpt, g_WpT);

    cudaFuncSetAttribute(tensor_gemm,
                         cudaFuncAttributeMaxDynamicSharedMemorySize, GEMM_SMEM_DYN);
    cudaFuncSetAttribute(attention_mma,
                         cudaFuncAttributeMaxDynamicSharedMemorySize, ATT_SMEM);

    const int n4x = (Mn * Cn) / 4;
    cvt_fp16<<<(n4x + 255) / 256, 256>>>(x, x16, n4x);
    transpose_cvt<<<dim3(N3 / 32, Kd / 32), 256>>>(W_attn, wat, N3);
    transpose_cvt<<<dim3(Cn / 32, Kd / 32), 256>>>(W_proj, wpt, Cn);

    // 1) qkv = x @ W_attn + b_attn   [8192, 2304]
    tensor_gemm<<<dim3(N3 / 128, Mn / 128), 256, GEMM_SMEM_DYN>>>(
        x16, wat, b_attn, qkv, N3);

    // 2) attention operand prep + pipelined flash attention
    attn_prep<<<dim3(Mn / 128, Hn), 256>>>();
    attention_mma<<<dim3(Tn / 128, Bn * Hn), 256, ATT_SMEM>>>();

    // 3) out = y @ W_proj + b_proj   [8192, 768]
    tensor_gemm<<<dim3(Cn / 128, Mn / 128), 256, GEMM_SMEM_DYN>>>(
        y16, wpt, b_proj, out, Cn);
}

// round 13
// speedup vs baseline: 2.2470x; 1.0711x over previous
#include <cuda_runtime.h>
#include <cuda_fp16.h>
#include <cstdint>

// Problem shape (fixed by the reference)
#define Bn 8
#define Tn 1024
#define Cn 768
#define Hn 8
#define Dn 96
#define Mn (Bn*Tn)      // 8192 rows
#define N3 (3*Cn)       // 2304
#define Kd 768

// ---------------------------------------------------------------------------
// Scratch (allocation-free rule: __device__ globals)
// ---------------------------------------------------------------------------
__device__ float g_qkv[(size_t)Mn * N3];   // [B*T, 3C] fp32
__device__ __half g_x16[(size_t)Mn * Cn];
__device__ __half g_y16[(size_t)Mn * Cn];
__device__ __half g_WaT[(size_t)N3 * Cn];  // W_attn^T [2304,768]
__device__ __half g_WpT[(size_t)Cn * Cn];  // W_proj^T [768,768]
// Attention operands: [bh][1024][96] for Q,K; [bh][96][1024] for V^T
#define AQE ((size_t)Bn * Hn * Tn * Dn)
__device__ __half g_Q16[AQE], g_K16[AQE], g_VT16[AQE];

// ---------------------------------------------------------------------------
// Portable tensor-core primitives (sm_80+, legal at .target sm_103)
// ---------------------------------------------------------------------------
__device__ __forceinline__ uint32_t smem_u32(const void* p) {
    uint32_t a;
    asm("{ .reg .u64 t; cvta.to.shared.u64 t, %1; cvt.u32.u64 %0, t; }" : "=r"(a) : "l"(p));
    return a;
}
__device__ __forceinline__ void ldsm_x4(uint32_t* r, uint32_t addr) {
    asm volatile("ldmatrix.sync.aligned.m8n8.x4.shared.b16 {%0,%1,%2,%3}, [%4];"
                 : "=r"(r[0]), "=r"(r[1]), "=r"(r[2]), "=r"(r[3]) : "r"(addr));
}
__device__ __forceinline__ void mma_16816(float* c, const uint32_t* a, const uint32_t* b) {
    asm volatile("mma.sync.aligned.m16n8k16.row.col.f32.f16.f16.f32 "
                 "{%0,%1,%2,%3}, {%4,%5,%6,%7}, {%8,%9}, {%0,%1,%2,%3};"
                 : "+f"(c[0]), "+f"(c[1]), "+f"(c[2]), "+f"(c[3])
                 : "r"(a[0]), "r"(a[1]), "r"(a[2]), "r"(a[3]), "r"(b[0]), "r"(b[1]));
}
__device__ __forceinline__ void cp16(uint32_t saddr, const void* g) {
    asm volatile("cp.async.cg.shared.global [%0], [%1], 16;" :: "r"(saddr), "l"(g));
}
#define CP_COMMIT() asm volatile("cp.async.commit_group;" ::: "memory")
#define CP_WAIT0()  asm volatile("cp.async.wait_group 0;" ::: "memory")
#define CP_WAIT1()  asm volatile("cp.async.wait_group 1;" ::: "memory")

__device__ __forceinline__ uint32_t pack2h(float a, float b) {
    __half2 p = __floats2half2_rn(a, b);
    return *(uint32_t*)&p;
}

// ---------------------------------------------------------------------------
// Conversion kernels
// ---------------------------------------------------------------------------
__global__ __launch_bounds__(256)
void cvt_fp16(const float* __restrict__ src, __half* __restrict__ dst, int n4)
{
    int i = blockIdx.x * blockDim.x + threadIdx.x;
    if (i >= n4) return;
    float4 v = ((const float4*)src)[i];
    ((uint32_t*)dst)[i * 2]     = pack2h(v.x, v.y);
    ((uint32_t*)dst)[i * 2 + 1] = pack2h(v.z, v.w);
}

// W[K=768, Ndim] row-major -> transposed fp16 [Ndim, 768]
__global__ __launch_bounds__(256)
void transpose_cvt(const float* __restrict__ W, __half* __restrict__ T, int Ndim)
{
    __shared__ float t[32][33];
    int tx = threadIdx.x & 31, ty = threadIdx.x >> 5;
    int n0 = blockIdx.x * 32, k0 = blockIdx.y * 32;
#pragma unroll
    for (int i = 0; i < 32; i += 8)
        t[ty + i][tx] = W[(size_t)(k0 + ty + i) * Ndim + n0 + tx];
    __syncthreads();
#pragma unroll
    for (int i = 0; i < 32; i += 8)
        T[(size_t)(n0 + ty + i) * Kd + k0 + tx] = __float2half_rn(t[tx][ty + i]);
}

// qkv fp32 -> attention operands: Q16 (pre-scaled), K16, VT16 (transposed)
__global__ __launch_bounds__(256)
void attn_prep()
{
    __shared__ float vs[128][101];
    const int tt = blockIdx.x;     // token tile 0..63 (global over 8192)
    const int h  = blockIdx.y;     // head
    const int tid = threadIdx.x;
    const int b = tt >> 3;
    const int bh = b * Hn + h;
    const int tloc = (tt & 7) * 128;
    const float* base = g_qkv + (size_t)tt * 128 * N3 + h * Dn;
    const float scale = rsqrtf((float)Dn);

    uint32_t* Q2 = (uint32_t*)(g_Q16 + ((size_t)bh * Tn + tloc) * Dn);
    uint32_t* K2 = (uint32_t*)(g_K16 + ((size_t)bh * Tn + tloc) * Dn);

    for (int i = tid; i < 128 * 24; i += 256) {
        int row = i / 24, j = i - row * 24;
        const float* p = base + (size_t)row * N3 + j * 4;
        float4 q = *(const float4*)(p);
        float4 k = *(const float4*)(p + Cn);
        float4 v = *(const float4*)(p + 2 * Cn);
        int o = row * 48 + j * 2;
        Q2[o]     = pack2h(q.x * scale, q.y * scale);
        Q2[o + 1] = pack2h(q.z * scale, q.w * scale);
        K2[o]     = pack2h(k.x, k.y);
        K2[o + 1] = pack2h(k.z, k.w);
        vs[row][j * 4 + 0] = v.x; vs[row][j * 4 + 1] = v.y;
        vs[row][j * 4 + 2] = v.z; vs[row][j * 4 + 3] = v.w;
    }
    __syncthreads();
    for (int i = tid; i < 96 * 64; i += 256) {
        int d = i >> 6, tp = i & 63;
        size_t o = (((size_t)bh * Dn + d) * Tn + tloc) / 2 + tp;
        ((uint32_t*)g_VT16)[o] = pack2h(vs[2 * tp][d], vs[2 * tp + 1][d]);
    }
}

// ---------------------------------------------------------------------------
// Tensor-core GEMM via mma.sync, fp16, fp32 accumulate.  Templated on the
// CTA N-tile BN: 128x BN tile, 8 warps (2 M-groups x 4 N-groups), warp tile
// 64 x BN/4.  3-stage cp.async pipeline, BK=64, one __syncthreads per K-tile.
// Smem rows 144B (9x16B): chunk index 9r mod 8 is a permutation ->
// conflict-free ldmatrix.
// ---------------------------------------------------------------------------
#define ROWB 144
#define ATILEB (128 * ROWB)

extern __shared__ float sm_dyn[];

template<int BN>
__device__ __forceinline__ void gemm_issue_stage(
    const __half* A, const __half* B, uint32_t sdst, int kt, int tid)
{
#pragma unroll
    for (int i = 0; i < 4; i++) {                 // A: 128 rows x 8 chunks
        int id = i * 256 + tid;
        int r = id >> 3, c = id & 7;
        cp16(sdst + r * ROWB + c * 16, A + (size_t)r * Kd + kt * 64 + c * 8);
    }
#pragma unroll
    for (int i = 0; i < BN / 32; i++) {           // B: BN rows x 8 chunks
        int id = i * 256 + tid;
        int r = id >> 3, c = id & 7;
        cp16(sdst + ATILEB + r * ROWB + c * 16, B + (size_t)r * Kd + kt * 64 + c * 8);
    }
    CP_COMMIT();
}

template<int BN>
__global__ __launch_bounds__(256, 1)
void tensor_gemm(const __half* __restrict__ A, const __half* __restrict__ BT,
                 const float* __restrict__ bias, float* __restrict__ Cout, int Ndim)
{
    constexpr int NF = BN / 32;          // n fragments (8-wide) per warp
    constexpr int STAGEB = ATILEB + BN * ROWB;

    const int tid = threadIdx.x;
    const int wid = tid >> 5, lane = tid & 31;
    const int m0 = blockIdx.y * 128;
    const int n0 = blockIdx.x * BN;
    const int wm = (wid >> 2) * 64;
    const int wn = (wid & 3) * (BN / 4);

    const uint32_t sbase = smem_u32(sm_dyn);
    const __half* Ab_g = A + (size_t)m0 * Kd;
    const __half* Bb_g = BT + (size_t)n0 * Kd;

    float acc[4][NF][4];
#pragma unroll
    for (int mf = 0; mf < 4; mf++)
#pragma unroll
        for (int nf = 0; nf < NF; nf++)
#pragma unroll
            for (int j = 0; j < 4; j++) acc[mf][nf][j] = 0.f;

    const int arow = wm + (lane & 15);
    const int akb  = (lane >> 4) << 3;
    const int brow = wn + (lane & 7) + ((lane >> 4) << 3);
    const int bkb  = ((lane >> 3) & 1) << 3;

    gemm_issue_stage<BN>(Ab_g, Bb_g, sbase, 0, tid);
    gemm_issue_stage<BN>(Ab_g, Bb_g, sbase + STAGEB, 1, tid);

    for (int kt = 0; kt < 12; kt++) {
        if (kt < 11) CP_WAIT1(); else CP_WAIT0();
        __syncthreads();

        if (kt + 2 < 12)
            gemm_issue_stage<BN>(Ab_g, Bb_g, sbase + ((kt + 2) % 3) * STAGEB, kt + 2, tid);

        const uint32_t Ab = sbase + (kt % 3) * STAGEB;
        const uint32_t Bb = Ab + ATILEB;

#pragma unroll
        for (int kf = 0; kf < 4; kf++) {
            const int kb = kf * 16;
            uint32_t a4[4][4], b4[NF][2];
#pragma unroll
            for (int mf = 0; mf < 4; mf++)
                ldsm_x4(a4[mf], Ab + (uint32_t)(arow + mf * 16) * ROWB + (kb + akb) * 2);
#pragma unroll
            for (int np = 0; np < NF / 2; np++) {
                uint32_t t4[4];
                ldsm_x4(t4, Bb + (uint32_t)(brow + np * 16) * ROWB + (kb + bkb) * 2);
                b4[2 * np][0] = t4[0]; b4[2 * np][1] = t4[1];
                b4[2 * np + 1][0] = t4[2]; b4[2 * np + 1][1] = t4[3];
            }
#pragma unroll
            for (int mf = 0; mf < 4; mf++)
#pragma unroll
                for (int nf = 0; nf < NF; nf++)
                    mma_16816(acc[mf][nf], a4[mf], b4[nf]);
        }
    }

    const int mrow = m0 + wm + (lane >> 2);
    const int ncol = n0 + wn + (lane & 3) * 2;
#pragma unroll
    for (int mf = 0; mf < 4; mf++)
#pragma unroll
        for (int nf = 0; nf < NF; nf++) {
            int r = mrow + mf * 16, c = ncol + nf * 8;
            float b0 = bias[c], b1 = bias[c + 1];
            *(float2*)(Cout + (size_t)r * Ndim + c) =
                make_float2(acc[mf][nf][0] + b0, acc[mf][nf][1] + b1);
            *(float2*)(Cout + (size_t)(r + 8) * Ndim + c) =
                make_float2(acc[mf][nf][2] + b0, acc[mf][nf][3] + b1);
        }
}

#define GEMM_SMEM_256 (3 * (ATILEB + 256 * ROWB))   // 165888 B
#define GEMM_SMEM_128 (3 * (ATILEB + 128 * ROWB))   // 110592 B

// ---------------------------------------------------------------------------
// Tensor-core flash attention, fp16 (unchanged from R12 passing kernel).
// K double-buffered, V staggered; qt reversed (long CTAs first).
// ---------------------------------------------------------------------------
#define SQp 208
#define SVp 272
#define AOFF_Q 0
#define AOFF_K (128 * SQp)
#define KSTGB  (128 * SQp)
#define AOFF_V (AOFF_K + 2 * KSTGB)
#define ATT_SMEM (AOFF_V + 96 * SVp)   // 105984 B

__device__ __forceinline__ void att_load_K(uint32_t kbase, const __half* kh, int tid)
{
    for (int i = tid; i < 128 * 12; i += 256) {
        int r = i / 12, c = i - r * 12;
        cp16(kbase + r * SQp + c * 16, kh + r * Dn + c * 8);
    }
    CP_COMMIT();
}
__device__ __forceinline__ void att_load_V(uint32_t sb, const __half* gV, int kt, int tid)
{
    for (int i = tid; i < 96 * 16; i += 256) {
        int d = i >> 4, c = i & 15;
        cp16(sb + AOFF_V + d * SVp + c * 16, gV + (size_t)d * Tn + kt * 128 + c * 8);
    }
    CP_COMMIT();
}

__global__ __launch_bounds__(256, 1)
void attention_mma()
{
    const int tid = threadIdx.x, lane = tid & 31, w = tid >> 5;
    const int qt = gridDim.x - 1 - blockIdx.x;   // long CTAs first
    const int bh = blockIdx.y;
    const int b = bh >> 3, h = bh & 7;
    const uint32_t sb = smem_u32(sm_dyn);

    const __half* gQ = g_Q16 + ((size_t)bh * Tn + qt * 128) * Dn;
    const __half* gK = g_K16 + (size_t)bh * Tn * Dn;
    const __half* gV = g_VT16 + (size_t)bh * Dn * Tn;

    for (int i = tid; i < 128 * 12; i += 256) {
        int r = i / 12, c = i - r * 12;
        cp16(sb + AOFF_Q + r * SQp + c * 16, gQ + r * Dn + c * 8);
        cp16(sb + AOFF_K + r * SQp + c * 16, gK + r * Dn + c * 8);
    }
    CP_COMMIT();
    att_load_V(sb, gV, 0, tid);

    float oacc[12][4];
#pragma unroll
    for (int i = 0; i < 12; i++)
#pragma unroll
        for (int j = 0; j < 4; j++) oacc[i][j] = 0.f;
    float m0 = -1e30f, m1 = -1e30f, l0 = 0.f, l1 = 0.f;

    for (int kt = 0; kt <= qt; kt++) {
        CP_WAIT1();
        __syncthreads();

        if (kt < qt)
            att_load_K(sb + AOFF_K + ((kt + 1) & 1) * KSTGB,
                       gK + (size_t)(kt + 1) * 128 * Dn, tid);

        const uint32_t Kb = sb + AOFF_K + (kt & 1) * KSTGB;

        float sacc[16][4];
#pragma unroll
        for (int i = 0; i < 16; i++)
#pragma unroll
            for (int j = 0; j < 4; j++) sacc[i][j] = 0.f;

#pragma unroll
        for (int kf = 0; kf < 6; kf++) {
            uint32_t qoff = (uint32_t)(w * 16 + (lane & 15)) * SQp + kf * 32 + (lane >> 4) * 16;
            uint32_t a4[4];
            ldsm_x4(a4, sb + AOFF_Q + qoff);
#pragma unroll
            for (int p = 0; p < 8; p++) {
                uint32_t k4[4];
                ldsm_x4(k4, Kb + (uint32_t)(p * 16 + (lane & 15)) * SQp + kf * 32 + (lane >> 4) * 16);
                uint32_t b0[2] = {k4[0], k4[2]}, b1[2] = {k4[1], k4[3]};
                mma_16816(sacc[2 * p],     a4, b0);
                mma_16816(sacc[2 * p + 1], a4, b1);
            }
        }

        if (kt == qt) {
            const int lr0 = w * 16 + (lane >> 2), lr1 = lr0 + 8;
#pragma unroll
            for (int nf = 0; nf < 16; nf++) {
                int lc = nf * 8 + (lane & 3) * 2;
                if (lc     > lr0) sacc[nf][0] = -1e30f;
                if (lc + 1 > lr0) sacc[nf][1] = -1e30f;
                if (lc     > lr1) sacc[nf][2] = -1e30f;
                if (lc + 1 > lr1) sacc[nf][3] = -1e30f;
            }
        }

        float tm0 = -1e30f, tm1 = -1e30f;
#pragma unroll
        for (int nf = 0; nf < 16; nf++) {
            tm0 = fmaxf(tm0, fmaxf(sacc[nf][0], sacc[nf][1]));
            tm1 = fmaxf(tm1, fmaxf(sacc[nf][2], sacc[nf][3]));
        }
        tm0 = fmaxf(tm0, __shfl_xor_sync(0xffffffffu, tm0, 1));
        tm0 = fmaxf(tm0, __shfl_xor_sync(0xffffffffu, tm0, 2));
        tm1 = fmaxf(tm1, __shfl_xor_sync(0xffffffffu, tm1, 1));
        tm1 = fmaxf(tm1, __shfl_xor_sync(0xffffffffu, tm1, 2));
        float nm0 = fmaxf(m0, tm0), nm1 = fmaxf(m1, tm1);
        float c0 = __expf(m0 - nm0), c1 = __expf(m1 - nm1);
        m0 = nm0; m1 = nm1;
        float ts0 = 0.f, ts1 = 0.f;
#pragma unroll
        for (int nf = 0; nf < 16; nf++) {
            sacc[nf][0] = __expf(sacc[nf][0] - nm0);
            sacc[nf][1] = __expf(sacc[nf][1] - nm0);
            sacc[nf][2] = __expf(sacc[nf][2] - nm1);
            sacc[nf][3] = __expf(sacc[nf][3] - nm1);
            ts0 += sacc[nf][0] + sacc[nf][1];
            ts1 += sacc[nf][2] + sacc[nf][3];
        }
        ts0 += __shfl_xor_sync(0xffffffffu, ts0, 1);
        ts0 += __shfl_xor_sync(0xffffffffu, ts0, 2);
        ts1 += __shfl_xor_sync(0xffffffffu, ts1, 1);
        ts1 += __shfl_xor_sync(0xffffffffu, ts1, 2);
        l0 = l0 * c0 + ts0;
        l1 = l1 * c1 + ts1;
#pragma unroll
        for (int nf = 0; nf < 12; nf++) {
            oacc[nf][0] *= c0; oacc[nf][1] *= c0;
            oacc[nf][2] *= c1; oacc[nf][3] *= c1;
        }

        if (kt < qt) CP_WAIT1(); else CP_WAIT0();
        __syncthreads();

#pragma unroll
        for (int t = 0; t < 8; t++) {
            uint32_t pa[4];
            pa[0] = pack2h(sacc[2 * t][0],     sacc[2 * t][1]);
            pa[1] = pack2h(sacc[2 * t][2],     sacc[2 * t][3]);
            pa[2] = pack2h(sacc[2 * t + 1][0], sacc[2 * t + 1][1]);
            pa[3] = pack2h(sacc[2 * t + 1][2], sacc[2 * t + 1][3]);
#pragma unroll
            for (int dp = 0; dp < 6; dp++) {
                uint32_t v4[4];
                ldsm_x4(v4, sb + AOFF_V + (uint32_t)(dp * 16 + (lane & 15)) * SVp
                               + t * 32 + (lane >> 4) * 16);
                uint32_t b0[2] = {v4[0], v4[2]}, b1[2] = {v4[1], v4[3]};
                mma_16816(oacc[2 * dp],     pa, b0);
                mma_16816(oacc[2 * dp + 1], pa, b1);
            }
        }

        __syncthreads();
        if (kt < qt)
            att_load_V(sb, gV, kt + 1, tid);
    }

    const float i0 = 1.f / l0, i1 = 1.f / l1;
    const size_t row0 = (size_t)b * Tn + qt * 128 + w * 16 + (lane >> 2);
#pragma unroll
    for (int nf = 0; nf < 12; nf++) {
        int col = h * Dn + nf * 8 + (lane & 3) * 2;
        *(uint32_t*)(g_y16 + row0 * Cn + col) =
            pack2h(oacc[nf][0] * i0, oacc[nf][1] * i0);
        *(uint32_t*)(g_y16 + (row0 + 8) * Cn + col) =
            pack2h(oacc[nf][2] * i1, oacc[nf][3] * i1);
    }
}

// ---------------------------------------------------------------------------
// Launch pipeline
// ---------------------------------------------------------------------------
extern "C" void kernel_launch(void* const* d_in, const int* in_sizes, int n_in,
                              void* d_out, int out_size)
{
    const float* x      = (const float*)d_in[0];
    const float* W_attn = (const float*)d_in[1];
    const float* b_attn = (const float*)d_in[2];
    const float* W_proj = (const float*)d_in[3];
    const float* b_proj = (const float*)d_in[4];
    float* out = (float*)d_out;

    float* qkv;
    __half *x16, *y16, *wat, *wpt;
    cudaGetSymbolAddress((void**)&qkv, g_qkv);
    cudaGetSymbolAddress((void**)&x16, g_x16);
    cudaGetSymbolAddress((void**)&y16, g_y16);
    cudaGetSymbolAddress((void**)&wat, g_WaT);
    cudaGetSymbolAddress((void**)&wpt, g_WpT);

    cudaFuncSetAttribute(tensor_gemm<256>,
                         cudaFuncAttributeMaxDynamicSharedMemorySize, GEMM_SMEM_256);
    cudaFuncSetAttribute(tensor_gemm<128>,
                         cudaFuncAttributeMaxDynamicSharedMemorySize, GEMM_SMEM_128);
    cudaFuncSetAttribute(attention_mma,
                         cudaFuncAttributeMaxDynamicSharedMemorySize, ATT_SMEM);

    const int n4x = (Mn * Cn) / 4;
    cvt_fp16<<<(n4x + 255) / 256, 256>>>(x, x16, n4x);
    transpose_cvt<<<dim3(N3 / 32, Kd / 32), 256>>>(W_attn, wat, N3);
    transpose_cvt<<<dim3(Cn / 32, Kd / 32), 256>>>(W_proj, wpt, Cn);

    // 1) qkv = x @ W_attn + b_attn   [8192, 2304]  (BN=256: 576 CTAs, 4 waves)
    tensor_gemm<256><<<dim3(N3 / 256, Mn / 128), 256, GEMM_SMEM_256>>>(
        x16, wat, b_attn, qkv, N3);

    // 2) attention operand prep + pipelined flash attention
    attn_prep<<<dim3(Mn / 128, Hn), 256>>>();
    attention_mma<<<dim3(Tn / 128, Bn * Hn), 256, ATT_SMEM>>>();

    // 3) out = y @ W_proj + b_proj   [8192, 768]  (BN=128: 384 CTAs)
    tensor_gemm<128><<<dim3(Cn / 128, Mn / 128), 256, GEMM_SMEM_128>>>(
        y16, wpt, b_proj, out, Cn);
}

// round 14
// speedup vs baseline: 2.4599x; 1.0948x over previous
#include <cuda_runtime.h>
#include <cuda_fp16.h>
#include <cstdint>

// Problem shape (fixed by the reference)
#define Bn 8
#define Tn 1024
#define Cn 768
#define Hn 8
#define Dn 96
#define Mn (Bn*Tn)      // 8192 rows
#define N3 (3*Cn)       // 2304
#define Kd 768

// ---------------------------------------------------------------------------
// Scratch (allocation-free rule: __device__ globals)
// ---------------------------------------------------------------------------
__device__ __half g_x16[(size_t)Mn * Cn];
__device__ __half g_y16[(size_t)Mn * Cn];
__device__ __half g_WaT[(size_t)N3 * Cn];  // W_attn^T [2304,768]
__device__ __half g_WpT[(size_t)Cn * Cn];  // W_proj^T [768,768]
// Attention operands, all [bh][1024][96] row-major fp16
#define AQE ((size_t)Bn * Hn * Tn * Dn)
__device__ __half g_Q16[AQE], g_K16[AQE], g_V16[AQE];

// ---------------------------------------------------------------------------
// Portable tensor-core primitives (sm_80+, legal at .target sm_103)
// ---------------------------------------------------------------------------
__device__ __forceinline__ uint32_t smem_u32(const void* p) {
    uint32_t a;
    asm("{ .reg .u64 t; cvta.to.shared.u64 t, %1; cvt.u32.u64 %0, t; }" : "=r"(a) : "l"(p));
    return a;
}
__device__ __forceinline__ void ldsm_x4(uint32_t* r, uint32_t addr) {
    asm volatile("ldmatrix.sync.aligned.m8n8.x4.shared.b16 {%0,%1,%2,%3}, [%4];"
                 : "=r"(r[0]), "=r"(r[1]), "=r"(r[2]), "=r"(r[3]) : "r"(addr));
}
__device__ __forceinline__ void ldsm_x4_trans(uint32_t* r, uint32_t addr) {
    asm volatile("ldmatrix.sync.aligned.m8n8.x4.trans.shared.b16 {%0,%1,%2,%3}, [%4];"
                 : "=r"(r[0]), "=r"(r[1]), "=r"(r[2]), "=r"(r[3]) : "r"(addr));
}
__device__ __forceinline__ void mma_16816(float* c, const uint32_t* a, const uint32_t* b) {
    asm volatile("mma.sync.aligned.m16n8k16.row.col.f32.f16.f16.f32 "
                 "{%0,%1,%2,%3}, {%4,%5,%6,%7}, {%8,%9}, {%0,%1,%2,%3};"
                 : "+f"(c[0]), "+f"(c[1]), "+f"(c[2]), "+f"(c[3])
                 : "r"(a[0]), "r"(a[1]), "r"(a[2]), "r"(a[3]), "r"(b[0]), "r"(b[1]));
}
__device__ __forceinline__ void cp16(uint32_t saddr, const void* g) {
    asm volatile("cp.async.cg.shared.global [%0], [%1], 16;" :: "r"(saddr), "l"(g));
}
#define CP_COMMIT() asm volatile("cp.async.commit_group;" ::: "memory")
#define CP_WAIT0()  asm volatile("cp.async.wait_group 0;" ::: "memory")
#define CP_WAIT1()  asm volatile("cp.async.wait_group 1;" ::: "memory")

__device__ __forceinline__ uint32_t pack2h(float a, float b) {
    __half2 p = __floats2half2_rn(a, b);
    return *(uint32_t*)&p;
}

// ---------------------------------------------------------------------------
// Conversion kernels
// ---------------------------------------------------------------------------
__global__ __launch_bounds__(256)
void cvt_fp16(const float* __restrict__ src, __half* __restrict__ dst, int n4)
{
    int i = blockIdx.x * blockDim.x + threadIdx.x;
    if (i >= n4) return;
    float4 v = ((const float4*)src)[i];
    ((uint32_t*)dst)[i * 2]     = pack2h(v.x, v.y);
    ((uint32_t*)dst)[i * 2 + 1] = pack2h(v.z, v.w);
}

// W[K=768, Ndim] row-major -> transposed fp16 [Ndim, 768]
__global__ __launch_bounds__(256)
void transpose_cvt(const float* __restrict__ W, __half* __restrict__ T, int Ndim)
{
    __shared__ float t[32][33];
    int tx = threadIdx.x & 31, ty = threadIdx.x >> 5;
    int n0 = blockIdx.x * 32, k0 = blockIdx.y * 32;
#pragma unroll
    for (int i = 0; i < 32; i += 8)
        t[ty + i][tx] = W[(size_t)(k0 + ty + i) * Ndim + n0 + tx];
    __syncthreads();
#pragma unroll
    for (int i = 0; i < 32; i += 8)
        T[(size_t)(n0 + ty + i) * Kd + k0 + tx] = __float2half_rn(t[tx][ty + i]);
}

// ---------------------------------------------------------------------------
// GEMM geometry shared constants
// ---------------------------------------------------------------------------
#define ROWB 144
#define ATILEB (128 * ROWB)

extern __shared__ float sm_dyn[];

template<int BN>
__device__ __forceinline__ void gemm_issue_stage(
    const __half* A, const __half* B, uint32_t sdst, int kt, int tid)
{
#pragma unroll
    for (int i = 0; i < 4; i++) {                 // A: 128 rows x 8 chunks
        int id = i * 256 + tid;
        int r = id >> 3, c = id & 7;
        cp16(sdst + r * ROWB + c * 16, A + (size_t)r * Kd + kt * 64 + c * 8);
    }
#pragma unroll
    for (int i = 0; i < BN / 32; i++) {           // B: BN rows x 8 chunks
        int id = i * 256 + tid;
        int r = id >> 3, c = id & 7;
        cp16(sdst + ATILEB + r * ROWB + c * 16, B + (size_t)r * Kd + kt * 64 + c * 8);
    }
    CP_COMMIT();
}

// ---------------------------------------------------------------------------
// Fused QKV GEMM: qkv = x @ W_attn^T-tiles + b_attn, epilogue writes fp16
// DIRECTLY into attention layouts (Q pre-scaled, K, V all [bh][t][96]).
// BN=256 hardcoded; each 256-wide n-tile lies wholly in q, k, or v.
// ---------------------------------------------------------------------------
#define QKV_STAGEB (ATILEB + 256 * ROWB)
#define QKV_SMEM (3 * QKV_STAGEB)     // 165888 B

__global__ __launch_bounds__(256, 1)
void qkv_gemm(const __half* __restrict__ A, const __half* __restrict__ BT,
              const float* __restrict__ bias)
{
    constexpr int NF = 8;
    const int tid = threadIdx.x;
    const int wid = tid >> 5, lane = tid & 31;
    const int m0 = blockIdx.y * 128;
    const int n0 = blockIdx.x * 256;
    const int wm = (wid >> 2) * 64;
    const int wn = (wid & 3) * 64;

    const uint32_t sbase = smem_u32(sm_dyn);
    const __half* Ab_g = A + (size_t)m0 * Kd;
    const __half* Bb_g = BT + (size_t)n0 * Kd;

    float acc[4][NF][4];
#pragma unroll
    for (int mf = 0; mf < 4; mf++)
#pragma unroll
        for (int nf = 0; nf < NF; nf++)
#pragma unroll
            for (int j = 0; j < 4; j++) acc[mf][nf][j] = 0.f;

    const int arow = wm + (lane & 15);
    const int akb  = (lane >> 4) << 3;
    const int brow = wn + (lane & 7) + ((lane >> 4) << 3);
    const int bkb  = ((lane >> 3) & 1) << 3;

    gemm_issue_stage<256>(Ab_g, Bb_g, sbase, 0, tid);
    gemm_issue_stage<256>(Ab_g, Bb_g, sbase + QKV_STAGEB, 1, tid);

    for (int kt = 0; kt < 12; kt++) {
        if (kt < 11) CP_WAIT1(); else CP_WAIT0();
        __syncthreads();

        if (kt + 2 < 12)
            gemm_issue_stage<256>(Ab_g, Bb_g, sbase + ((kt + 2) % 3) * QKV_STAGEB, kt + 2, tid);

        const uint32_t Ab = sbase + (kt % 3) * QKV_STAGEB;
        const uint32_t Bb = Ab + ATILEB;

#pragma unroll
        for (int kf = 0; kf < 4; kf++) {
            const int kb = kf * 16;
            uint32_t a4[4][4], b4[NF][2];
#pragma unroll
            for (int mf = 0; mf < 4; mf++)
                ldsm_x4(a4[mf], Ab + (uint32_t)(arow + mf * 16) * ROWB + (kb + akb) * 2);
#pragma unroll
            for (int np = 0; np < NF / 2; np++) {
                uint32_t t4[4];
                ldsm_x4(t4, Bb + (uint32_t)(brow + np * 16) * ROWB + (kb + bkb) * 2);
                b4[2 * np][0] = t4[0]; b4[2 * np][1] = t4[1];
                b4[2 * np + 1][0] = t4[2]; b4[2 * np + 1][1] = t4[3];
            }
#pragma unroll
            for (int mf = 0; mf < 4; mf++)
#pragma unroll
                for (int nf = 0; nf < NF; nf++)
                    mma_16816(acc[mf][nf], a4[mf], b4[nf]);
        }
    }

    // Fused epilogue: fp16 into attention layout [bh][t][96]
    const int sec = n0 / Cn;                          // 0=q, 1=k, 2=v (uniform)
    __half* dst = (sec == 0) ? g_Q16 : (sec == 1) ? g_K16 : g_V16;
    const float scale = (sec == 0) ? rsqrtf((float)Dn) : 1.f;

    const int mrow = m0 + wm + (lane >> 2);
    const int ncol = n0 + wn + (lane & 3) * 2;
#pragma unroll
    for (int mf = 0; mf < 4; mf++)
#pragma unroll
        for (int nf = 0; nf < NF; nf++) {
            int r = mrow + mf * 16;
            int c = ncol + nf * 8;
            int cs = c - sec * Cn;
            int h = cs / Dn, d = cs - h * Dn;        // d even, pair in-head
            float b0 = bias[c], b1 = bias[c + 1];
            int b = r >> 10, t = r & 1023;
            size_t off = (((size_t)(b * Hn + h) * Tn + t) * Dn + d);
            *(uint32_t*)(dst + off) =
                pack2h((acc[mf][nf][0] + b0) * scale, (acc[mf][nf][1] + b1) * scale);
            *(uint32_t*)(dst + off + (size_t)8 * Dn) =
                pack2h((acc[mf][nf][2] + b0) * scale, (acc[mf][nf][3] + b1) * scale);
        }
}

// ---------------------------------------------------------------------------
// Generic tensor GEMM (BN template) — used for the projection (BN=128).
// ---------------------------------------------------------------------------
template<int BN>
__global__ __launch_bounds__(256, 1)
void tensor_gemm(const __half* __restrict__ A, const __half* __restrict__ BT,
                 const float* __restrict__ bias, float* __restrict__ Cout, int Ndim)
{
    constexpr int NF = BN / 32;
    constexpr int STAGEB = ATILEB + BN * ROWB;

    const int tid = threadIdx.x;
    const int wid = tid >> 5, lane = tid & 31;
    const int m0 = blockIdx.y * 128;
    const int n0 = blockIdx.x * BN;
    const int wm = (wid >> 2) * 64;
    const int wn = (wid & 3) * (BN / 4);

    const uint32_t sbase = smem_u32(sm_dyn);
    const __half* Ab_g = A + (size_t)m0 * Kd;
    const __half* Bb_g = BT + (size_t)n0 * Kd;

    float acc[4][NF][4];
#pragma unroll
    for (int mf = 0; mf < 4; mf++)
#pragma unroll
        for (int nf = 0; nf < NF; nf++)
#pragma unroll
            for (int j = 0; j < 4; j++) acc[mf][nf][j] = 0.f;

    const int arow = wm + (lane & 15);
    const int akb  = (lane >> 4) << 3;
    const int brow = wn + (lane & 7) + ((lane >> 4) << 3);
    const int bkb  = ((lane >> 3) & 1) << 3;

    gemm_issue_stage<BN>(Ab_g, Bb_g, sbase, 0, tid);
    gemm_issue_stage<BN>(Ab_g, Bb_g, sbase + STAGEB, 1, tid);

    for (int kt = 0; kt < 12; kt++) {
        if (kt < 11) CP_WAIT1(); else CP_WAIT0();
        __syncthreads();

        if (kt + 2 < 12)
            gemm_issue_stage<BN>(Ab_g, Bb_g, sbase + ((kt + 2) % 3) * STAGEB, kt + 2, tid);

        const uint32_t Ab = sbase + (kt % 3) * STAGEB;
        const uint32_t Bb = Ab + ATILEB;

#pragma unroll
        for (int kf = 0; kf < 4; kf++) {
            const int kb = kf * 16;
            uint32_t a4[4][4], b4[NF][2];
#pragma unroll
            for (int mf = 0; mf < 4; mf++)
                ldsm_x4(a4[mf], Ab + (uint32_t)(arow + mf * 16) * ROWB + (kb + akb) * 2);
#pragma unroll
            for (int np = 0; np < NF / 2; np++) {
                uint32_t t4[4];
                ldsm_x4(t4, Bb + (uint32_t)(brow + np * 16) * ROWB + (kb + bkb) * 2);
                b4[2 * np][0] = t4[0]; b4[2 * np][1] = t4[1];
                b4[2 * np + 1][0] = t4[2]; b4[2 * np + 1][1] = t4[3];
            }
#pragma unroll
            for (int mf = 0; mf < 4; mf++)
#pragma unroll
                for (int nf = 0; nf < NF; nf++)
                    mma_16816(acc[mf][nf], a4[mf], b4[nf]);
        }
    }

    const int mrow = m0 + wm + (lane >> 2);
    const int ncol = n0 + wn + (lane & 3) * 2;
#pragma unroll
    for (int mf = 0; mf < 4; mf++)
#pragma unroll
        for (int nf = 0; nf < NF; nf++) {
            int r = mrow + mf * 16, c = ncol + nf * 8;
            float b0 = bias[c], b1 = bias[c + 1];
            *(float2*)(Cout + (size_t)r * Ndim + c) =
                make_float2(acc[mf][nf][0] + b0, acc[mf][nf][1] + b1);
            *(float2*)(Cout + (size_t)(r + 8) * Ndim + c) =
                make_float2(acc[mf][nf][2] + b0, acc[mf][nf][3] + b1);
        }
}

#define GEMM_SMEM_128 (3 * (ATILEB + 128 * ROWB))   // 110592 B

// ---------------------------------------------------------------------------
// Tensor-core flash attention, fp16.  V stored row-major [bh][t][96] (same
// layout as K) and loaded for PV via ldmatrix.x4.trans.
// K double-buffered, V staggered; qt reversed (long CTAs first).
// smem: Q + 2xK + V = 4 x 26624 = 106496 B
// ---------------------------------------------------------------------------
#define SQp 208
#define AOFF_Q 0
#define AOFF_K (128 * SQp)
#define KSTGB  (128 * SQp)
#define AOFF_V (AOFF_K + 2 * KSTGB)
#define ATT_SMEM (AOFF_V + 128 * SQp)   // 106496 B

__device__ __forceinline__ void att_load_tile(uint32_t sdst, const __half* g, int tid)
{
    for (int i = tid; i < 128 * 12; i += 256) {
        int r = i / 12, c = i - r * 12;
        cp16(sdst + r * SQp + c * 16, g + r * Dn + c * 8);
    }
    CP_COMMIT();
}

__global__ __launch_bounds__(256, 1)
void attention_mma()
{
    const int tid = threadIdx.x, lane = tid & 31, w = tid >> 5;
    const int qt = gridDim.x - 1 - blockIdx.x;   // long CTAs first
    const int bh = blockIdx.y;
    const int b = bh >> 3, h = bh & 7;
    const uint32_t sb = smem_u32(sm_dyn);

    const __half* gQ = g_Q16 + ((size_t)bh * Tn + qt * 128) * Dn;
    const __half* gK = g_K16 + (size_t)bh * Tn * Dn;
    const __half* gV = g_V16 + (size_t)bh * Tn * Dn;

    // Preamble: Q + K0 as one group, V0 as second group
    for (int i = tid; i < 128 * 12; i += 256) {
        int r = i / 12, c = i - r * 12;
        cp16(sb + AOFF_Q + r * SQp + c * 16, gQ + r * Dn + c * 8);
        cp16(sb + AOFF_K + r * SQp + c * 16, gK + r * Dn + c * 8);
    }
    CP_COMMIT();
    att_load_tile(sb + AOFF_V, gV, tid);

    float oacc[12][4];
#pragma unroll
    for (int i = 0; i < 12; i++)
#pragma unroll
        for (int j = 0; j < 4; j++) oacc[i][j] = 0.f;
    float m0 = -1e30f, m1 = -1e30f, l0 = 0.f, l1 = 0.f;

    for (int kt = 0; kt <= qt; kt++) {
        CP_WAIT1();
        __syncthreads();

        if (kt < qt)
            att_load_tile(sb + AOFF_K + ((kt + 1) & 1) * KSTGB,
                          gK + (size_t)(kt + 1) * 128 * Dn, tid);

        const uint32_t Kb = sb + AOFF_K + (kt & 1) * KSTGB;

        // ---- S = Q K^T ----
        float sacc[16][4];
#pragma unroll
        for (int i = 0; i < 16; i++)
#pragma unroll
            for (int j = 0; j < 4; j++) sacc[i][j] = 0.f;

#pragma unroll
        for (int kf = 0; kf < 6; kf++) {
            uint32_t qoff = (uint32_t)(w * 16 + (lane & 15)) * SQp + kf * 32 + (lane >> 4) * 16;
            uint32_t a4[4];
            ldsm_x4(a4, sb + AOFF_Q + qoff);
#pragma unroll
            for (int p = 0; p < 8; p++) {
                uint32_t k4[4];
                ldsm_x4(k4, Kb + (uint32_t)(p * 16 + (lane & 15)) * SQp + kf * 32 + (lane >> 4) * 16);
                uint32_t b0[2] = {k4[0], k4[2]}, b1[2] = {k4[1], k4[3]};
                mma_16816(sacc[2 * p],     a4, b0);
                mma_16816(sacc[2 * p + 1], a4, b1);
            }
        }

        if (kt == qt) {
            const int lr0 = w * 16 + (lane >> 2), lr1 = lr0 + 8;
#pragma unroll
            for (int nf = 0; nf < 16; nf++) {
                int lc = nf * 8 + (lane & 3) * 2;
                if (lc     > lr0) sacc[nf][0] = -1e30f;
                if (lc + 1 > lr0) sacc[nf][1] = -1e30f;
                if (lc     > lr1) sacc[nf][2] = -1e30f;
                if (lc + 1 > lr1) sacc[nf][3] = -1e30f;
            }
        }

        // ---- online softmax ----
        float tm0 = -1e30f, tm1 = -1e30f;
#pragma unroll
        for (int nf = 0; nf < 16; nf++) {
            tm0 = fmaxf(tm0, fmaxf(sacc[nf][0], sacc[nf][1]));
            tm1 = fmaxf(tm1, fmaxf(sacc[nf][2], sacc[nf][3]));
        }
        tm0 = fmaxf(tm0, __shfl_xor_sync(0xffffffffu, tm0, 1));
        tm0 = fmaxf(tm0, __shfl_xor_sync(0xffffffffu, tm0, 2));
        tm1 = fmaxf(tm1, __shfl_xor_sync(0xffffffffu, tm1, 1));
        tm1 = fmaxf(tm1, __shfl_xor_sync(0xffffffffu, tm1, 2));
        float nm0 = fmaxf(m0, tm0), nm1 = fmaxf(m1, tm1);
        float c0 = __expf(m0 - nm0), c1 = __expf(m1 - nm1);
        m0 = nm0; m1 = nm1;
        float ts0 = 0.f, ts1 = 0.f;
#pragma unroll
        for (int nf = 0; nf < 16; nf++) {
            sacc[nf][0] = __expf(sacc[nf][0] - nm0);
            sacc[nf][1] = __expf(sacc[nf][1] - nm0);
            sacc[nf][2] = __expf(sacc[nf][2] - nm1);
            sacc[nf][3] = __expf(sacc[nf][3] - nm1);
            ts0 += sacc[nf][0] + sacc[nf][1];
            ts1 += sacc[nf][2] + sacc[nf][3];
        }
        ts0 += __shfl_xor_sync(0xffffffffu, ts0, 1);
        ts0 += __shfl_xor_sync(0xffffffffu, ts0, 2);
        ts1 += __shfl_xor_sync(0xffffffffu, ts1, 1);
        ts1 += __shfl_xor_sync(0xffffffffu, ts1, 2);
        l0 = l0 * c0 + ts0;
        l1 = l1 * c1 + ts1;
#pragma unroll
        for (int nf = 0; nf < 12; nf++) {
            oacc[nf][0] *= c0; oacc[nf][1] *= c0;
            oacc[nf][2] *= c1; oacc[nf][3] *= c1;
        }

        // wait V(kt): only K(kt+1) may remain in flight
        if (kt < qt) CP_WAIT1(); else CP_WAIT0();
        __syncthreads();

        // ---- O += P V   (V row-major [t][d], trans-ldmatrix B fragments) ----
        const uint32_t Vb = sb + AOFF_V;
#pragma unroll
        for (int t = 0; t < 8; t++) {
            uint32_t pa[4];
            pa[0] = pack2h(sacc[2 * t][0],     sacc[2 * t][1]);
            pa[1] = pack2h(sacc[2 * t][2],     sacc[2 * t][3]);
            pa[2] = pack2h(sacc[2 * t + 1][0], sacc[2 * t + 1][1]);
            pa[3] = pack2h(sacc[2 * t + 1][2], sacc[2 * t + 1][3]);
#pragma unroll
            for (int dg = 0; dg < 6; dg++) {
                uint32_t v4[4];
                ldsm_x4_trans(v4, Vb + (uint32_t)(t * 16 + (lane & 15)) * SQp
                                     + dg * 32 + (lane >> 4) * 16);
                uint32_t b0[2] = {v4[0], v4[1]}, b1[2] = {v4[2], v4[3]};
                mma_16816(oacc[2 * dg],     pa, b0);
                mma_16816(oacc[2 * dg + 1], pa, b1);
            }
        }

        // all warps done reading V(kt) -> safe to overwrite
        __syncthreads();
        if (kt < qt)
            att_load_tile(sb + AOFF_V, gV + (size_t)(kt + 1) * 128 * Dn, tid);
    }

    // ---- epilogue: normalize, write y fp16 [B*T, C] ----
    const float i0 = 1.f / l0, i1 = 1.f / l1;
    const size_t row0 = (size_t)b * Tn + qt * 128 + w * 16 + (lane >> 2);
#pragma unroll
    for (int nf = 0; nf < 12; nf++) {
        int col = h * Dn + nf * 8 + (lane & 3) * 2;
        *(uint32_t*)(g_y16 + row0 * Cn + col) =
            pack2h(oacc[nf][0] * i0, oacc[nf][1] * i0);
        *(uint32_t*)(g_y16 + (row0 + 8) * Cn + col) =
            pack2h(oacc[nf][2] * i1, oacc[nf][3] * i1);
    }
}

// ---------------------------------------------------------------------------
// Launch pipeline
// ---------------------------------------------------------------------------
extern "C" void kernel_launch(void* const* d_in, const int* in_sizes, int n_in,
                              void* d_out, int out_size)
{
    const float* x      = (const float*)d_in[0];
    const float* W_attn = (const float*)d_in[1];
    const float* b_attn = (const float*)d_in[2];
    const float* W_proj = (const float*)d_in[3];
    const float* b_proj = (const float*)d_in[4];
    float* out = (float*)d_out;

    __half *x16, *y16, *wat, *wpt;
    cudaGetSymbolAddress((void**)&x16, g_x16);
    cudaGetSymbolAddress((void**)&y16, g_y16);
    cudaGetSymbolAddress((void**)&wat, g_WaT);
    cudaGetSymbolAddress((void**)&wpt, g_WpT);

    cudaFuncSetAttribute(qkv_gemm,
                         cudaFuncAttributeMaxDynamicSharedMemorySize, QKV_SMEM);
    cudaFuncSetAttribute(tensor_gemm<128>,
                         cudaFuncAttributeMaxDynamicSharedMemorySize, GEMM_SMEM_128);
    cudaFuncSetAttribute(attention_mma,
                         cudaFuncAttributeMaxDynamicSharedMemorySize, ATT_SMEM);

    const int n4x = (Mn * Cn) / 4;
    cvt_fp16<<<(n4x + 255) / 256, 256>>>(x, x16, n4x);
    transpose_cvt<<<dim3(N3 / 32, Kd / 32), 256>>>(W_attn, wat, N3);
    transpose_cvt<<<dim3(Cn / 32, Kd / 32), 256>>>(W_proj, wpt, Cn);

    // 1) fused qkv GEMM -> Q16/K16/V16 directly (no fp32 qkv, no prep kernel)
    qkv_gemm<<<dim3(N3 / 256, Mn / 128), 256, QKV_SMEM>>>(x16, wat, b_attn);

    // 2) pipelined flash attention (tensor cores)
    attention_mma<<<dim3(Tn / 128, Bn * Hn), 256, ATT_SMEM>>>();

    // 3) out = y @ W_proj + b_proj   [8192, 768]
    tensor_gemm<128><<<dim3(Cn / 128, Mn / 128), 256, GEMM_SMEM_128>>>(
        y16, wpt, b_proj, out, Cn);
}

// round 15
// speedup vs baseline: 2.6137x; 1.0625x over previous
#include <cuda_runtime.h>
#include <cuda_fp16.h>
#include <cstdint>

// Problem shape (fixed by the reference)
#define Bn 8
#define Tn 1024
#define Cn 768
#define Hn 8
#define Dn 96
#define Mn (Bn*Tn)      // 8192 rows
#define N3 (3*Cn)       // 2304
#define Kd 768

// ---------------------------------------------------------------------------
// Scratch (allocation-free rule: __device__ globals)
// ---------------------------------------------------------------------------
__device__ __half g_x16[(size_t)Mn * Cn];
__device__ __half g_y16[(size_t)Mn * Cn];
__device__ __half g_WaT[(size_t)N3 * Cn];  // W_attn^T [2304,768]
__device__ __half g_WpT[(size_t)Cn * Cn];  // W_proj^T [768,768]
// Attention operands, all [bh][1024][96] row-major fp16
#define AQE ((size_t)Bn * Hn * Tn * Dn)
__device__ __half g_Q16[AQE], g_K16[AQE], g_V16[AQE];

// ---------------------------------------------------------------------------
// Portable tensor-core primitives (sm_80+, legal at .target sm_103)
// ---------------------------------------------------------------------------
__device__ __forceinline__ uint32_t smem_u32(const void* p) {
    uint32_t a;
    asm("{ .reg .u64 t; cvta.to.shared.u64 t, %1; cvt.u32.u64 %0, t; }" : "=r"(a) : "l"(p));
    return a;
}
__device__ __forceinline__ void ldsm_x4(uint32_t* r, uint32_t addr) {
    asm volatile("ldmatrix.sync.aligned.m8n8.x4.shared.b16 {%0,%1,%2,%3}, [%4];"
                 : "=r"(r[0]), "=r"(r[1]), "=r"(r[2]), "=r"(r[3]) : "r"(addr));
}
__device__ __forceinline__ void ldsm_x4_trans(uint32_t* r, uint32_t addr) {
    asm volatile("ldmatrix.sync.aligned.m8n8.x4.trans.shared.b16 {%0,%1,%2,%3}, [%4];"
                 : "=r"(r[0]), "=r"(r[1]), "=r"(r[2]), "=r"(r[3]) : "r"(addr));
}
__device__ __forceinline__ void mma_16816(float* c, const uint32_t* a, const uint32_t* b) {
    asm volatile("mma.sync.aligned.m16n8k16.row.col.f32.f16.f16.f32 "
                 "{%0,%1,%2,%3}, {%4,%5,%6,%7}, {%8,%9}, {%0,%1,%2,%3};"
                 : "+f"(c[0]), "+f"(c[1]), "+f"(c[2]), "+f"(c[3])
                 : "r"(a[0]), "r"(a[1]), "r"(a[2]), "r"(a[3]), "r"(b[0]), "r"(b[1]));
}
__device__ __forceinline__ void cp16(uint32_t saddr, const void* g) {
    asm volatile("cp.async.cg.shared.global [%0], [%1], 16;" :: "r"(saddr), "l"(g));
}
#define CP_COMMIT() asm volatile("cp.async.commit_group;" ::: "memory")
#define CP_WAIT0()  asm volatile("cp.async.wait_group 0;" ::: "memory")
#define CP_WAIT1()  asm volatile("cp.async.wait_group 1;" ::: "memory")

__device__ __forceinline__ uint32_t pack2h(float a, float b) {
    __half2 p = __floats2half2_rn(a, b);
    return *(uint32_t*)&p;
}

// ---------------------------------------------------------------------------
// Fused prep: x -> fp16 | W_attn^T fp16 | W_proj^T fp16, one launch.
// Blocks [0, 6144): cvt; [6144, 7872): W_attn transpose; [7872, 8448): W_proj.
// ---------------------------------------------------------------------------
#define PREP_CVT_BLKS  ((Mn * Cn / 4) / 256)          // 6144
#define PREP_WA_BLKS   ((N3 / 32) * (Kd / 32))        // 1728
#define PREP_WP_BLKS   ((Cn / 32) * (Kd / 32))        // 576
#define PREP_BLKS      (PREP_CVT_BLKS + PREP_WA_BLKS + PREP_WP_BLKS)

__device__ __forceinline__ void transpose_tile(const float* __restrict__ W,
                                               __half* __restrict__ T,
                                               int Ndim, int bx, int by, int tid)
{
    __shared__ float t[32][33];
    int tx = tid & 31, ty = tid >> 5;
    int n0 = bx * 32, k0 = by * 32;
#pragma unroll
    for (int i = 0; i < 32; i += 8)
        t[ty + i][tx] = W[(size_t)(k0 + ty + i) * Ndim + n0 + tx];
    __syncthreads();
#pragma unroll
    for (int i = 0; i < 32; i += 8)
        T[(size_t)(n0 + ty + i) * Kd + k0 + tx] = __float2half_rn(t[tx][ty + i]);
}

__global__ __launch_bounds__(256)
void prep_all(const float* __restrict__ x, const float* __restrict__ Wa,
              const float* __restrict__ Wp)
{
    const int blk = blockIdx.x, tid = threadIdx.x;
    if (blk < PREP_CVT_BLKS) {
        int i = blk * 256 + tid;
        float4 v = ((const float4*)x)[i];
        ((uint32_t*)g_x16)[i * 2]     = pack2h(v.x, v.y);
        ((uint32_t*)g_x16)[i * 2 + 1] = pack2h(v.z, v.w);
    } else if (blk < PREP_CVT_BLKS + PREP_WA_BLKS) {
        int b = blk - PREP_CVT_BLKS;
        transpose_tile(Wa, g_WaT, N3, b % (N3 / 32), b / (N3 / 32), tid);
    } else {
        int b = blk - PREP_CVT_BLKS - PREP_WA_BLKS;
        transpose_tile(Wp, g_WpT, Cn, b % (Cn / 32), b / (Cn / 32), tid);
    }
}

// ---------------------------------------------------------------------------
// GEMM geometry shared constants
// ---------------------------------------------------------------------------
#define ROWB 144
#define ATILEB (128 * ROWB)

extern __shared__ float sm_dyn[];

template<int BN>
__device__ __forceinline__ void gemm_issue_stage(
    const __half* A, const __half* B, uint32_t sdst, int kt, int tid)
{
#pragma unroll
    for (int i = 0; i < 4; i++) {                 // A: 128 rows x 8 chunks
        int id = i * 256 + tid;
        int r = id >> 3, c = id & 7;
        cp16(sdst + r * ROWB + c * 16, A + (size_t)r * Kd + kt * 64 + c * 8);
    }
#pragma unroll
    for (int i = 0; i < BN / 32; i++) {           // B: BN rows x 8 chunks
        int id = i * 256 + tid;
        int r = id >> 3, c = id & 7;
        cp16(sdst + ATILEB + r * ROWB + c * 16, B + (size_t)r * Kd + kt * 64 + c * 8);
    }
    CP_COMMIT();
}

// ---------------------------------------------------------------------------
// Fused QKV GEMM (unchanged from R14): BN=256, epilogue writes fp16 directly
// into attention layouts (Q pre-scaled, K, V all [bh][t][96]).
// ---------------------------------------------------------------------------
#define QKV_STAGEB (ATILEB + 256 * ROWB)
#define QKV_SMEM (3 * QKV_STAGEB)     // 165888 B

__global__ __launch_bounds__(256, 1)
void qkv_gemm(const __half* __restrict__ A, const __half* __restrict__ BT,
              const float* __restrict__ bias)
{
    constexpr int NF = 8;
    const int tid = threadIdx.x;
    const int wid = tid >> 5, lane = tid & 31;
    const int m0 = blockIdx.y * 128;
    const int n0 = blockIdx.x * 256;
    const int wm = (wid >> 2) * 64;
    const int wn = (wid & 3) * 64;

    const uint32_t sbase = smem_u32(sm_dyn);
    const __half* Ab_g = A + (size_t)m0 * Kd;
    const __half* Bb_g = BT + (size_t)n0 * Kd;

    float acc[4][NF][4];
#pragma unroll
    for (int mf = 0; mf < 4; mf++)
#pragma unroll
        for (int nf = 0; nf < NF; nf++)
#pragma unroll
            for (int j = 0; j < 4; j++) acc[mf][nf][j] = 0.f;

    const int arow = wm + (lane & 15);
    const int akb  = (lane >> 4) << 3;
    const int brow = wn + (lane & 7) + ((lane >> 4) << 3);
    const int bkb  = ((lane >> 3) & 1) << 3;

    gemm_issue_stage<256>(Ab_g, Bb_g, sbase, 0, tid);
    gemm_issue_stage<256>(Ab_g, Bb_g, sbase + QKV_STAGEB, 1, tid);

    for (int kt = 0; kt < 12; kt++) {
        if (kt < 11) CP_WAIT1(); else CP_WAIT0();
        __syncthreads();

        if (kt + 2 < 12)
            gemm_issue_stage<256>(Ab_g, Bb_g, sbase + ((kt + 2) % 3) * QKV_STAGEB, kt + 2, tid);

        const uint32_t Ab = sbase + (kt % 3) * QKV_STAGEB;
        const uint32_t Bb = Ab + ATILEB;

#pragma unroll
        for (int kf = 0; kf < 4; kf++) {
            const int kb = kf * 16;
            uint32_t a4[4][4], b4[NF][2];
#pragma unroll
            for (int mf = 0; mf < 4; mf++)
                ldsm_x4(a4[mf], Ab + (uint32_t)(arow + mf * 16) * ROWB + (kb + akb) * 2);
#pragma unroll
            for (int np = 0; np < NF / 2; np++) {
                uint32_t t4[4];
                ldsm_x4(t4, Bb + (uint32_t)(brow + np * 16) * ROWB + (kb + bkb) * 2);
                b4[2 * np][0] = t4[0]; b4[2 * np][1] = t4[1];
                b4[2 * np + 1][0] = t4[2]; b4[2 * np + 1][1] = t4[3];
            }
#pragma unroll
            for (int mf = 0; mf < 4; mf++)
#pragma unroll
                for (int nf = 0; nf < NF; nf++)
                    mma_16816(acc[mf][nf], a4[mf], b4[nf]);
        }
    }

    const int sec = n0 / Cn;                          // 0=q, 1=k, 2=v (uniform)
    __half* dst = (sec == 0) ? g_Q16 : (sec == 1) ? g_K16 : g_V16;
    const float scale = (sec == 0) ? rsqrtf((float)Dn) : 1.f;

    const int mrow = m0 + wm + (lane >> 2);
    const int ncol = n0 + wn + (lane & 3) * 2;
#pragma unroll
    for (int mf = 0; mf < 4; mf++)
#pragma unroll
        for (int nf = 0; nf < NF; nf++) {
            int r = mrow + mf * 16;
            int c = ncol + nf * 8;
            int cs = c - sec * Cn;
            int h = cs / Dn, d = cs - h * Dn;
            float b0 = bias[c], b1 = bias[c + 1];
            int b = r >> 10, t = r & 1023;
            size_t off = (((size_t)(b * Hn + h) * Tn + t) * Dn + d);
            *(uint32_t*)(dst + off) =
                pack2h((acc[mf][nf][0] + b0) * scale, (acc[mf][nf][1] + b1) * scale);
            *(uint32_t*)(dst + off + (size_t)8 * Dn) =
                pack2h((acc[mf][nf][2] + b0) * scale, (acc[mf][nf][3] + b1) * scale);
        }
}

// ---------------------------------------------------------------------------
// Generic tensor GEMM (BN template) — used for the projection (BN=128).
// ---------------------------------------------------------------------------
template<int BN>
__global__ __launch_bounds__(256, 1)
void tensor_gemm(const __half* __restrict__ A, const __half* __restrict__ BT,
                 const float* __restrict__ bias, float* __restrict__ Cout, int Ndim)
{
    constexpr int NF = BN / 32;
    constexpr int STAGEB = ATILEB + BN * ROWB;

    const int tid = threadIdx.x;
    const int wid = tid >> 5, lane = tid & 31;
    const int m0 = blockIdx.y * 128;
    const int n0 = blockIdx.x * BN;
    const int wm = (wid >> 2) * 64;
    const int wn = (wid & 3) * (BN / 4);

    const uint32_t sbase = smem_u32(sm_dyn);
    const __half* Ab_g = A + (size_t)m0 * Kd;
    const __half* Bb_g = BT + (size_t)n0 * Kd;

    float acc[4][NF][4];
#pragma unroll
    for (int mf = 0; mf < 4; mf++)
#pragma unroll
        for (int nf = 0; nf < NF; nf++)
#pragma unroll
            for (int j = 0; j < 4; j++) acc[mf][nf][j] = 0.f;

    const int arow = wm + (lane & 15);
    const int akb  = (lane >> 4) << 3;
    const int brow = wn + (lane & 7) + ((lane >> 4) << 3);
    const int bkb  = ((lane >> 3) & 1) << 3;

    gemm_issue_stage<BN>(Ab_g, Bb_g, sbase, 0, tid);
    gemm_issue_stage<BN>(Ab_g, Bb_g, sbase + STAGEB, 1, tid);

    for (int kt = 0; kt < 12; kt++) {
        if (kt < 11) CP_WAIT1(); else CP_WAIT0();
        __syncthreads();

        if (kt + 2 < 12)
            gemm_issue_stage<BN>(Ab_g, Bb_g, sbase + ((kt + 2) % 3) * STAGEB, kt + 2, tid);

        const uint32_t Ab = sbase + (kt % 3) * STAGEB;
        const uint32_t Bb = Ab + ATILEB;

#pragma unroll
        for (int kf = 0; kf < 4; kf++) {
            const int kb = kf * 16;
            uint32_t a4[4][4], b4[NF][2];
#pragma unroll
            for (int mf = 0; mf < 4; mf++)
                ldsm_x4(a4[mf], Ab + (uint32_t)(arow + mf * 16) * ROWB + (kb + akb) * 2);
#pragma unroll
            for (int np = 0; np < NF / 2; np++) {
                uint32_t t4[4];
                ldsm_x4(t4, Bb + (uint32_t)(brow + np * 16) * ROWB + (kb + bkb) * 2);
                b4[2 * np][0] = t4[0]; b4[2 * np][1] = t4[1];
                b4[2 * np + 1][0] = t4[2]; b4[2 * np + 1][1] = t4[3];
            }
#pragma unroll
            for (int mf = 0; mf < 4; mf++)
#pragma unroll
                for (int nf = 0; nf < NF; nf++)
                    mma_16816(acc[mf][nf], a4[mf], b4[nf]);
        }
    }

    const int mrow = m0 + wm + (lane >> 2);
    const int ncol = n0 + wn + (lane & 3) * 2;
#pragma unroll
    for (int mf = 0; mf < 4; mf++)
#pragma unroll
        for (int nf = 0; nf < NF; nf++) {
            int r = mrow + mf * 16, c = ncol + nf * 8;
            float b0 = bias[c], b1 = bias[c + 1];
            *(float2*)(Cout + (size_t)r * Ndim + c) =
                make_float2(acc[mf][nf][0] + b0, acc[mf][nf][1] + b1);
            *(float2*)(Cout + (size_t)(r + 8) * Ndim + c) =
                make_float2(acc[mf][nf][2] + b0, acc[mf][nf][3] + b1);
        }
}

#define GEMM_SMEM_128 (3 * (ATILEB + 128 * ROWB))   // 110592 B

// ---------------------------------------------------------------------------
// Tensor-core flash attention, fp16.
// NEW: K AND V double-buffered, ONE wait + ONE sync per K-tile (loads for
// kt+1 issued at top of iter kt, overlapping the whole compute); Q fragments
// preloaded into registers (no Q smem reads in the mainloop).
// smem: Q + 2xK + 2xV = 5 x 26624 = 133120 B
// ---------------------------------------------------------------------------
#define SQp 208
#define TILE_SM (128 * SQp)
#define AOFF_Q 0
#define AOFF_K TILE_SM
#define AOFF_V (AOFF_K + 2 * TILE_SM)
#define ATT_SMEM (AOFF_V + 2 * TILE_SM)   // 133120 B

__device__ __forceinline__ void att_load_KV(uint32_t sb, const __half* gK,
                                            const __half* gV, int kt, int tid)
{
    const uint32_t kb = sb + AOFF_K + (kt & 1) * TILE_SM;
    const uint32_t vb = sb + AOFF_V + (kt & 1) * TILE_SM;
    const __half* k = gK + (size_t)kt * 128 * Dn;
    const __half* v = gV + (size_t)kt * 128 * Dn;
    for (int i = tid; i < 128 * 12; i += 256) {
        int r = i / 12, c = i - r * 12;
        cp16(kb + r * SQp + c * 16, k + r * Dn + c * 8);
        cp16(vb + r * SQp + c * 16, v + r * Dn + c * 8);
    }
    CP_COMMIT();
}

__global__ __launch_bounds__(256, 1)
void attention_mma()
{
    const int tid = threadIdx.x, lane = tid & 31, w = tid >> 5;
    const int qt = gridDim.x - 1 - blockIdx.x;   // long CTAs first
    const int bh = blockIdx.y;
    const int b = bh >> 3, h = bh & 7;
    const uint32_t sb = smem_u32(sm_dyn);

    const __half* gQ = g_Q16 + ((size_t)bh * Tn + qt * 128) * Dn;
    const __half* gK = g_K16 + (size_t)bh * Tn * Dn;
    const __half* gV = g_V16 + (size_t)bh * Tn * Dn;

    // Preamble: Q + K0 + V0 as one commit group
    for (int i = tid; i < 128 * 12; i += 256) {
        int r = i / 12, c = i - r * 12;
        cp16(sb + AOFF_Q + r * SQp + c * 16, gQ + r * Dn + c * 8);
        cp16(sb + AOFF_K + r * SQp + c * 16, gK + r * Dn + c * 8);
        cp16(sb + AOFF_V + r * SQp + c * 16, gV + r * Dn + c * 8);
    }
    CP_COMMIT();
    CP_WAIT0();
    __syncthreads();

    // Q fragments live in registers for the whole kernel
    uint32_t qa[6][4];
#pragma unroll
    for (int kf = 0; kf < 6; kf++)
        ldsm_x4(qa[kf], sb + AOFF_Q +
                (uint32_t)(w * 16 + (lane & 15)) * SQp + kf * 32 + (lane >> 4) * 16);

    float oacc[12][4];
#pragma unroll
    for (int i = 0; i < 12; i++)
#pragma unroll
        for (int j = 0; j < 4; j++) oacc[i][j] = 0.f;
    float m0 = -1e30f, m1 = -1e30f, l0 = 0.f, l1 = 0.f;

    for (int kt = 0; kt <= qt; kt++) {
        // prefetch K(kt+1)+V(kt+1); overlaps ALL compute below
        if (kt < qt) att_load_KV(sb, gK, gV, kt + 1, tid);

        const uint32_t Kb = sb + AOFF_K + (kt & 1) * TILE_SM;
        const uint32_t Vb = sb + AOFF_V + (kt & 1) * TILE_SM;

        // ---- S = Q K^T ----
        float sacc[16][4];
#pragma unroll
        for (int i = 0; i < 16; i++)
#pragma unroll
            for (int j = 0; j < 4; j++) sacc[i][j] = 0.f;

#pragma unroll
        for (int kf = 0; kf < 6; kf++) {
#pragma unroll
            for (int p = 0; p < 8; p++) {
                uint32_t k4[4];
                ldsm_x4(k4, Kb + (uint32_t)(p * 16 + (lane & 15)) * SQp + kf * 32 + (lane >> 4) * 16);
                uint32_t b0[2] = {k4[0], k4[2]}, b1[2] = {k4[1], k4[3]};
                mma_16816(sacc[2 * p],     qa[kf], b0);
                mma_16816(sacc[2 * p + 1], qa[kf], b1);
            }
        }

        if (kt == qt) {
            const int lr0 = w * 16 + (lane >> 2), lr1 = lr0 + 8;
#pragma unroll
            for (int nf = 0; nf < 16; nf++) {
                int lc = nf * 8 + (lane & 3) * 2;
                if (lc     > lr0) sacc[nf][0] = -1e30f;
                if (lc + 1 > lr0) sacc[nf][1] = -1e30f;
                if (lc     > lr1) sacc[nf][2] = -1e30f;
                if (lc + 1 > lr1) sacc[nf][3] = -1e30f;
            }
        }

        // ---- online softmax ----
        float tm0 = -1e30f, tm1 = -1e30f;
#pragma unroll
        for (int nf = 0; nf < 16; nf++) {
            tm0 = fmaxf(tm0, fmaxf(sacc[nf][0], sacc[nf][1]));
            tm1 = fmaxf(tm1, fmaxf(sacc[nf][2], sacc[nf][3]));
        }
        tm0 = fmaxf(tm0, __shfl_xor_sync(0xffffffffu, tm0, 1));
        tm0 = fmaxf(tm0, __shfl_xor_sync(0xffffffffu, tm0, 2));
        tm1 = fmaxf(tm1, __shfl_xor_sync(0xffffffffu, tm1, 1));
        tm1 = fmaxf(tm1, __shfl_xor_sync(0xffffffffu, tm1, 2));
        float nm0 = fmaxf(m0, tm0), nm1 = fmaxf(m1, tm1);
        float c0 = __expf(m0 - nm0), c1 = __expf(m1 - nm1);
        m0 = nm0; m1 = nm1;
        float ts0 = 0.f, ts1 = 0.f;
#pragma unroll
        for (int nf = 0; nf < 16; nf++) {
            sacc[nf][0] = __expf(sacc[nf][0] - nm0);
            sacc[nf][1] = __expf(sacc[nf][1] - nm0);
            sacc[nf][2] = __expf(sacc[nf][2] - nm1);
            sacc[nf][3] = __expf(sacc[nf][3] - nm1);
            ts0 += sacc[nf][0] + sacc[nf][1];
            ts1 += sacc[nf][2] + sacc[nf][3];
        }
        ts0 += __shfl_xor_sync(0xffffffffu, ts0, 1);
        ts0 += __shfl_xor_sync(0xffffffffu, ts0, 2);
        ts1 += __shfl_xor_sync(0xffffffffu, ts1, 1);
        ts1 += __shfl_xor_sync(0xffffffffu, ts1, 2);
        l0 = l0 * c0 + ts0;
        l1 = l1 * c1 + ts1;
#pragma unroll
        for (int nf = 0; nf < 12; nf++) {
            oacc[nf][0] *= c0; oacc[nf][1] *= c0;
            oacc[nf][2] *= c1; oacc[nf][3] *= c1;
        }

        // ---- O += P V   (V row-major [t][d], trans-ldmatrix B fragments) ----
#pragma unroll
        for (int t = 0; t < 8; t++) {
            uint32_t pa[4];
            pa[0] = pack2h(sacc[2 * t][0],     sacc[2 * t][1]);
            pa[1] = pack2h(sacc[2 * t][2],     sacc[2 * t][3]);
            pa[2] = pack2h(sacc[2 * t + 1][0], sacc[2 * t + 1][1]);
            pa[3] = pack2h(sacc[2 * t + 1][2], sacc[2 * t + 1][3]);
#pragma unroll
            for (int dg = 0; dg < 6; dg++) {
                uint32_t v4[4];
                ldsm_x4_trans(v4, Vb + (uint32_t)(t * 16 + (lane & 15)) * SQp
                                     + dg * 32 + (lane >> 4) * 16);
                uint32_t b0[2] = {v4[0], v4[1]}, b1[2] = {v4[2], v4[3]};
                mma_16816(oacc[2 * dg],     pa, b0);
                mma_16816(oacc[2 * dg + 1], pa, b1);
            }
        }

        // single wait + sync per iter: K/V(kt+1) arrived, all warps done
        // with buffers (kt&1) -> safe for iter kt+1 to prefetch into them
        if (kt < qt) {
            CP_WAIT0();
            __syncthreads();
        }
    }

    // ---- epilogue: normalize, write y fp16 [B*T, C] ----
    const float i0 = 1.f / l0, i1 = 1.f / l1;
    const size_t row0 = (size_t)b * Tn + qt * 128 + w * 16 + (lane >> 2);
#pragma unroll
    for (int nf = 0; nf < 12; nf++) {
        int col = h * Dn + nf * 8 + (lane & 3) * 2;
        *(uint32_t*)(g_y16 + row0 * Cn + col) =
            pack2h(oacc[nf][0] * i0, oacc[nf][1] * i0);
        *(uint32_t*)(g_y16 + (row0 + 8) * Cn + col) =
            pack2h(oacc[nf][2] * i1, oacc[nf][3] * i1);
    }
}

// ---------------------------------------------------------------------------
// Launch pipeline
// ---------------------------------------------------------------------------
extern "C" void kernel_launch(void* const* d_in, const int* in_sizes, int n_in,
                              void* d_out, int out_size)
{
    const float* x      = (const float*)d_in[0];
    const float* W_attn = (const float*)d_in[1];
    const float* b_attn = (const float*)d_in[2];
    const float* W_proj = (const float*)d_in[3];
    const float* b_proj = (const float*)d_in[4];
    float* out = (float*)d_out;

    __half *x16, *y16, *wat, *wpt;
    cudaGetSymbolAddress((void**)&x16, g_x16);
    cudaGetSymbolAddress((void**)&y16, g_y16);
    cudaGetSymbolAddress((void**)&wat, g_WaT);
    cudaGetSymbolAddress((void**)&wpt, g_WpT);

    cudaFuncSetAttribute(qkv_gemm,
                         cudaFuncAttributeMaxDynamicSharedMemorySize, QKV_SMEM);
    cudaFuncSetAttribute(tensor_gemm<128>,
                         cudaFuncAttributeMaxDynamicSharedMemorySize, GEMM_SMEM_128);
    cudaFuncSetAttribute(attention_mma,
                         cudaFuncAttributeMaxDynamicSharedMemorySize, ATT_SMEM);

    // 0) fused input prep (x convert + both weight transposes, one launch)
    prep_all<<<PREP_BLKS, 256>>>(x, W_attn, W_proj);

    // 1) fused qkv GEMM -> Q16/K16/V16 directly
    qkv_gemm<<<dim3(N3 / 256, Mn / 128), 256, QKV_SMEM>>>(x16, wat, b_attn);

    // 2) pipelined flash attention (tensor cores)
    attention_mma<<<dim3(Tn / 128, Bn * Hn), 256, ATT_SMEM>>>();

    // 3) out = y @ W_proj + b_proj   [8192, 768]
    tensor_gemm<128><<<dim3(Cn / 128, Mn / 128), 256, GEMM_SMEM_128>>>(
        y16, wpt, b_proj, out, Cn);
}

// round 16
// speedup vs baseline: 2.6991x; 1.0326x over previous
#include <cuda_runtime.h>
#include <cuda_fp16.h>
#include <cstdint>

// Problem shape (fixed by the reference)
#define Bn 8
#define Tn 1024
#define Cn 768
#define Hn 8
#define Dn 96
#define Mn (Bn*Tn)      // 8192 rows
#define N3 (3*Cn)       // 2304
#define Kd 768

// ---------------------------------------------------------------------------
// Scratch (allocation-free rule: __device__ globals)
// ---------------------------------------------------------------------------
__device__ __half g_x16[(size_t)Mn * Cn];
__device__ __half g_y16[(size_t)Mn * Cn];
__device__ __half g_WaT[(size_t)N3 * Cn];  // W_attn^T [2304,768]
__device__ __half g_WpT[(size_t)Cn * Cn];  // W_proj^T [768,768]
// Attention operands, all [bh][1024][96] row-major fp16
#define AQE ((size_t)Bn * Hn * Tn * Dn)
__device__ __half g_Q16[AQE], g_K16[AQE], g_V16[AQE];

// ---------------------------------------------------------------------------
// Portable tensor-core primitives (sm_80+, legal at .target sm_103)
// ---------------------------------------------------------------------------
__device__ __forceinline__ uint32_t smem_u32(const void* p) {
    uint32_t a;
    asm("{ .reg .u64 t; cvta.to.shared.u64 t, %1; cvt.u32.u64 %0, t; }" : "=r"(a) : "l"(p));
    return a;
}
__device__ __forceinline__ void ldsm_x4(uint32_t* r, uint32_t addr) {
    asm volatile("ldmatrix.sync.aligned.m8n8.x4.shared.b16 {%0,%1,%2,%3}, [%4];"
                 : "=r"(r[0]), "=r"(r[1]), "=r"(r[2]), "=r"(r[3]) : "r"(addr));
}
__device__ __forceinline__ void ldsm_x4_trans(uint32_t* r, uint32_t addr) {
    asm volatile("ldmatrix.sync.aligned.m8n8.x4.trans.shared.b16 {%0,%1,%2,%3}, [%4];"
                 : "=r"(r[0]), "=r"(r[1]), "=r"(r[2]), "=r"(r[3]) : "r"(addr));
}
__device__ __forceinline__ void mma_16816(float* c, const uint32_t* a, const uint32_t* b) {
    asm volatile("mma.sync.aligned.m16n8k16.row.col.f32.f16.f16.f32 "
                 "{%0,%1,%2,%3}, {%4,%5,%6,%7}, {%8,%9}, {%0,%1,%2,%3};"
                 : "+f"(c[0]), "+f"(c[1]), "+f"(c[2]), "+f"(c[3])
                 : "r"(a[0]), "r"(a[1]), "r"(a[2]), "r"(a[3]), "r"(b[0]), "r"(b[1]));
}
__device__ __forceinline__ void cp16(uint32_t saddr, const void* g) {
    asm volatile("cp.async.cg.shared.global [%0], [%1], 16;" :: "r"(saddr), "l"(g));
}
#define CP_COMMIT() asm volatile("cp.async.commit_group;" ::: "memory")
#define CP_WAIT0()  asm volatile("cp.async.wait_group 0;" ::: "memory")
#define CP_WAIT1()  asm volatile("cp.async.wait_group 1;" ::: "memory")

__device__ __forceinline__ uint32_t pack2h(float a, float b) {
    __half2 p = __floats2half2_rn(a, b);
    return *(uint32_t*)&p;
}

// ---------------------------------------------------------------------------
// Fused prep: x -> fp16 | W_attn^T fp16 | W_proj^T fp16, one launch.
// ---------------------------------------------------------------------------
#define PREP_CVT_BLKS  ((Mn * Cn / 4) / 256)          // 6144
#define PREP_WA_BLKS   ((N3 / 32) * (Kd / 32))        // 1728
#define PREP_WP_BLKS   ((Cn / 32) * (Kd / 32))        // 576
#define PREP_BLKS      (PREP_CVT_BLKS + PREP_WA_BLKS + PREP_WP_BLKS)

__device__ __forceinline__ void transpose_tile(const float* __restrict__ W,
                                               __half* __restrict__ T,
                                               int Ndim, int bx, int by, int tid)
{
    __shared__ float t[32][33];
    int tx = tid & 31, ty = tid >> 5;
    int n0 = bx * 32, k0 = by * 32;
#pragma unroll
    for (int i = 0; i < 32; i += 8)
        t[ty + i][tx] = W[(size_t)(k0 + ty + i) * Ndim + n0 + tx];
    __syncthreads();
#pragma unroll
    for (int i = 0; i < 32; i += 8)
        T[(size_t)(n0 + ty + i) * Kd + k0 + tx] = __float2half_rn(t[tx][ty + i]);
}

__global__ __launch_bounds__(256)
void prep_all(const float* __restrict__ x, const float* __restrict__ Wa,
              const float* __restrict__ Wp)
{
    const int blk = blockIdx.x, tid = threadIdx.x;
    if (blk < PREP_CVT_BLKS) {
        int i = blk * 256 + tid;
        float4 v = ((const float4*)x)[i];
        ((uint32_t*)g_x16)[i * 2]     = pack2h(v.x, v.y);
        ((uint32_t*)g_x16)[i * 2 + 1] = pack2h(v.z, v.w);
    } else if (blk < PREP_CVT_BLKS + PREP_WA_BLKS) {
        int b = blk - PREP_CVT_BLKS;
        transpose_tile(Wa, g_WaT, N3, b % (N3 / 32), b / (N3 / 32), tid);
    } else {
        int b = blk - PREP_CVT_BLKS - PREP_WA_BLKS;
        transpose_tile(Wp, g_WpT, Cn, b % (Cn / 32), b / (Cn / 32), tid);
    }
}

// ---------------------------------------------------------------------------
// GEMM geometry shared constants
// ---------------------------------------------------------------------------
#define ROWB 144
#define ATILEB (128 * ROWB)

extern __shared__ float sm_dyn[];

template<int BN>
__device__ __forceinline__ void gemm_issue_stage(
    const __half* A, const __half* B, uint32_t sdst, int kt, int tid)
{
#pragma unroll
    for (int i = 0; i < 4; i++) {                 // A: 128 rows x 8 chunks
        int id = i * 256 + tid;
        int r = id >> 3, c = id & 7;
        cp16(sdst + r * ROWB + c * 16, A + (size_t)r * Kd + kt * 64 + c * 8);
    }
#pragma unroll
    for (int i = 0; i < BN / 32; i++) {           // B: BN rows x 8 chunks
        int id = i * 256 + tid;
        int r = id >> 3, c = id & 7;
        cp16(sdst + ATILEB + r * ROWB + c * 16, B + (size_t)r * Kd + kt * 64 + c * 8);
    }
    CP_COMMIT();
}

// ---------------------------------------------------------------------------
// Fused QKV GEMM (unchanged): BN=256, epilogue writes fp16 directly into
// attention layouts (Q pre-scaled, K, V all [bh][t][96]).
// ---------------------------------------------------------------------------
#define QKV_STAGEB (ATILEB + 256 * ROWB)
#define QKV_SMEM (3 * QKV_STAGEB)     // 165888 B

__global__ __launch_bounds__(256, 1)
void qkv_gemm(const __half* __restrict__ A, const __half* __restrict__ BT,
              const float* __restrict__ bias)
{
    constexpr int NF = 8;
    const int tid = threadIdx.x;
    const int wid = tid >> 5, lane = tid & 31;
    const int m0 = blockIdx.y * 128;
    const int n0 = blockIdx.x * 256;
    const int wm = (wid >> 2) * 64;
    const int wn = (wid & 3) * 64;

    const uint32_t sbase = smem_u32(sm_dyn);
    const __half* Ab_g = A + (size_t)m0 * Kd;
    const __half* Bb_g = BT + (size_t)n0 * Kd;

    float acc[4][NF][4];
#pragma unroll
    for (int mf = 0; mf < 4; mf++)
#pragma unroll
        for (int nf = 0; nf < NF; nf++)
#pragma unroll
            for (int j = 0; j < 4; j++) acc[mf][nf][j] = 0.f;

    const int arow = wm + (lane & 15);
    const int akb  = (lane >> 4) << 3;
    const int brow = wn + (lane & 7) + ((lane >> 4) << 3);
    const int bkb  = ((lane >> 3) & 1) << 3;

    gemm_issue_stage<256>(Ab_g, Bb_g, sbase, 0, tid);
    gemm_issue_stage<256>(Ab_g, Bb_g, sbase + QKV_STAGEB, 1, tid);

    for (int kt = 0; kt < 12; kt++) {
        if (kt < 11) CP_WAIT1(); else CP_WAIT0();
        __syncthreads();

        if (kt + 2 < 12)
            gemm_issue_stage<256>(Ab_g, Bb_g, sbase + ((kt + 2) % 3) * QKV_STAGEB, kt + 2, tid);

        const uint32_t Ab = sbase + (kt % 3) * QKV_STAGEB;
        const uint32_t Bb = Ab + ATILEB;

#pragma unroll
        for (int kf = 0; kf < 4; kf++) {
            const int kb = kf * 16;
            uint32_t a4[4][4], b4[NF][2];
#pragma unroll
            for (int mf = 0; mf < 4; mf++)
                ldsm_x4(a4[mf], Ab + (uint32_t)(arow + mf * 16) * ROWB + (kb + akb) * 2);
#pragma unroll
            for (int np = 0; np < NF / 2; np++) {
                uint32_t t4[4];
                ldsm_x4(t4, Bb + (uint32_t)(brow + np * 16) * ROWB + (kb + bkb) * 2);
                b4[2 * np][0] = t4[0]; b4[2 * np][1] = t4[1];
                b4[2 * np + 1][0] = t4[2]; b4[2 * np + 1][1] = t4[3];
            }
#pragma unroll
            for (int mf = 0; mf < 4; mf++)
#pragma unroll
                for (int nf = 0; nf < NF; nf++)
                    mma_16816(acc[mf][nf], a4[mf], b4[nf]);
        }
    }

    const int sec = n0 / Cn;                          // 0=q, 1=k, 2=v (uniform)
    __half* dst = (sec == 0) ? g_Q16 : (sec == 1) ? g_K16 : g_V16;
    const float scale = (sec == 0) ? rsqrtf((float)Dn) : 1.f;

    const int mrow = m0 + wm + (lane >> 2);
    const int ncol = n0 + wn + (lane & 3) * 2;
#pragma unroll
    for (int mf = 0; mf < 4; mf++)
#pragma unroll
        for (int nf = 0; nf < NF; nf++) {
            int r = mrow + mf * 16;
            int c = ncol + nf * 8;
            int cs = c - sec * Cn;
            int h = cs / Dn, d = cs - h * Dn;
            float b0 = bias[c], b1 = bias[c + 1];
            int b = r >> 10, t = r & 1023;
            size_t off = (((size_t)(b * Hn + h) * Tn + t) * Dn + d);
            *(uint32_t*)(dst + off) =
                pack2h((acc[mf][nf][0] + b0) * scale, (acc[mf][nf][1] + b1) * scale);
            *(uint32_t*)(dst + off + (size_t)8 * Dn) =
                pack2h((acc[mf][nf][2] + b0) * scale, (acc[mf][nf][3] + b1) * scale);
        }
}

// ---------------------------------------------------------------------------
// Projection GEMM: BN=128, __launch_bounds__(256, 2) -> 2 CTAs/SM so one
// CTA's MMAs cover the other's barriers/waits.  Smem 3x36864 = 110592 B/CTA
// (2 CTAs = 221184 B < 228 KB).  Reg cap 128/thread.
// ---------------------------------------------------------------------------
#define PROJ_STAGEB (ATILEB + 128 * ROWB)
#define PROJ_SMEM (3 * PROJ_STAGEB)   // 110592 B

__global__ __launch_bounds__(256, 2)
void proj_gemm(const __half* __restrict__ A, const __half* __restrict__ BT,
               const float* __restrict__ bias, float* __restrict__ Cout)
{
    constexpr int NF = 4;
    const int tid = threadIdx.x;
    const int wid = tid >> 5, lane = tid & 31;
    const int m0 = blockIdx.y * 128;
    const int n0 = blockIdx.x * 128;
    const int wm = (wid >> 2) * 64;
    const int wn = (wid & 3) * 32;

    const uint32_t sbase = smem_u32(sm_dyn);
    const __half* Ab_g = A + (size_t)m0 * Kd;
    const __half* Bb_g = BT + (size_t)n0 * Kd;

    float acc[4][NF][4];
#pragma unroll
    for (int mf = 0; mf < 4; mf++)
#pragma unroll
        for (int nf = 0; nf < NF; nf++)
#pragma unroll
            for (int j = 0; j < 4; j++) acc[mf][nf][j] = 0.f;

    const int arow = wm + (lane & 15);
    const int akb  = (lane >> 4) << 3;
    const int brow = wn + (lane & 7) + ((lane >> 4) << 3);
    const int bkb  = ((lane >> 3) & 1) << 3;

    gemm_issue_stage<128>(Ab_g, Bb_g, sbase, 0, tid);
    gemm_issue_stage<128>(Ab_g, Bb_g, sbase + PROJ_STAGEB, 1, tid);

    for (int kt = 0; kt < 12; kt++) {
        if (kt < 11) CP_WAIT1(); else CP_WAIT0();
        __syncthreads();

        if (kt + 2 < 12)
            gemm_issue_stage<128>(Ab_g, Bb_g, sbase + ((kt + 2) % 3) * PROJ_STAGEB, kt + 2, tid);

        const uint32_t Ab = sbase + (kt % 3) * PROJ_STAGEB;
        const uint32_t Bb = Ab + ATILEB;

#pragma unroll
        for (int kf = 0; kf < 4; kf++) {
            const int kb = kf * 16;
            uint32_t a4[4][4], b4[NF][2];
#pragma unroll
            for (int mf = 0; mf < 4; mf++)
                ldsm_x4(a4[mf], Ab + (uint32_t)(arow + mf * 16) * ROWB + (kb + akb) * 2);
#pragma unroll
            for (int np = 0; np < NF / 2; np++) {
                uint32_t t4[4];
                ldsm_x4(t4, Bb + (uint32_t)(brow + np * 16) * ROWB + (kb + bkb) * 2);
                b4[2 * np][0] = t4[0]; b4[2 * np][1] = t4[1];
                b4[2 * np + 1][0] = t4[2]; b4[2 * np + 1][1] = t4[3];
            }
#pragma unroll
            for (int mf = 0; mf < 4; mf++)
#pragma unroll
                for (int nf = 0; nf < NF; nf++)
                    mma_16816(acc[mf][nf], a4[mf], b4[nf]);
        }
    }

    const int mrow = m0 + wm + (lane >> 2);
    const int ncol = n0 + wn + (lane & 3) * 2;
#pragma unroll
    for (int mf = 0; mf < 4; mf++)
#pragma unroll
        for (int nf = 0; nf < NF; nf++) {
            int r = mrow + mf * 16, c = ncol + nf * 8;
            float b0 = bias[c], b1 = bias[c + 1];
            *(float2*)(Cout + (size_t)r * Cn + c) =
                make_float2(acc[mf][nf][0] + b0, acc[mf][nf][1] + b1);
            *(float2*)(Cout + (size_t)(r + 8) * Cn + c) =
                make_float2(acc[mf][nf][2] + b0, acc[mf][nf][3] + b1);
        }
}

// ---------------------------------------------------------------------------
// Tensor-core flash attention, fp16 (unchanged from R15 passing kernel).
// K+V double-buffered, one wait + one sync per K-tile; Q fragments in regs.
// smem: Q + 2xK + 2xV = 5 x 26624 = 133120 B
// ---------------------------------------------------------------------------
#define SQp 208
#define TILE_SM (128 * SQp)
#define AOFF_Q 0
#define AOFF_K TILE_SM
#define AOFF_V (AOFF_K + 2 * TILE_SM)
#define ATT_SMEM (AOFF_V + 2 * TILE_SM)   // 133120 B

__device__ __forceinline__ void att_load_KV(uint32_t sb, const __half* gK,
                                            const __half* gV, int kt, int tid)
{
    const uint32_t kb = sb + AOFF_K + (kt & 1) * TILE_SM;
    const uint32_t vb = sb + AOFF_V + (kt & 1) * TILE_SM;
    const __half* k = gK + (size_t)kt * 128 * Dn;
    const __half* v = gV + (size_t)kt * 128 * Dn;
    for (int i = tid; i < 128 * 12; i += 256) {
        int r = i / 12, c = i - r * 12;
        cp16(kb + r * SQp + c * 16, k + r * Dn + c * 8);
        cp16(vb + r * SQp + c * 16, v + r * Dn + c * 8);
    }
    CP_COMMIT();
}

__global__ __launch_bounds__(256, 1)
void attention_mma()
{
    const int tid = threadIdx.x, lane = tid & 31, w = tid >> 5;
    const int qt = gridDim.x - 1 - blockIdx.x;   // long CTAs first
    const int bh = blockIdx.y;
    const int b = bh >> 3, h = bh & 7;
    const uint32_t sb = smem_u32(sm_dyn);

    const __half* gQ = g_Q16 + ((size_t)bh * Tn + qt * 128) * Dn;
    const __half* gK = g_K16 + (size_t)bh * Tn * Dn;
    const __half* gV = g_V16 + (size_t)bh * Tn * Dn;

    for (int i = tid; i < 128 * 12; i += 256) {
        int r = i / 12, c = i - r * 12;
        cp16(sb + AOFF_Q + r * SQp + c * 16, gQ + r * Dn + c * 8);
        cp16(sb + AOFF_K + r * SQp + c * 16, gK + r * Dn + c * 8);
        cp16(sb + AOFF_V + r * SQp + c * 16, gV + r * Dn + c * 8);
    }
    CP_COMMIT();
    CP_WAIT0();
    __syncthreads();

    uint32_t qa[6][4];
#pragma unroll
    for (int kf = 0; kf < 6; kf++)
        ldsm_x4(qa[kf], sb + AOFF_Q +
                (uint32_t)(w * 16 + (lane & 15)) * SQp + kf * 32 + (lane >> 4) * 16);

    float oacc[12][4];
#pragma unroll
    for (int i = 0; i < 12; i++)
#pragma unroll
        for (int j = 0; j < 4; j++) oacc[i][j] = 0.f;
    float m0 = -1e30f, m1 = -1e30f, l0 = 0.f, l1 = 0.f;

    for (int kt = 0; kt <= qt; kt++) {
        if (kt < qt) att_load_KV(sb, gK, gV, kt + 1, tid);

        const uint32_t Kb = sb + AOFF_K + (kt & 1) * TILE_SM;
        const uint32_t Vb = sb + AOFF_V + (kt & 1) * TILE_SM;

        // ---- S = Q K^T ----
        float sacc[16][4];
#pragma unroll
        for (int i = 0; i < 16; i++)
#pragma unroll
            for (int j = 0; j < 4; j++) sacc[i][j] = 0.f;

#pragma unroll
        for (int kf = 0; kf < 6; kf++) {
#pragma unroll
            for (int p = 0; p < 8; p++) {
                uint32_t k4[4];
                ldsm_x4(k4, Kb + (uint32_t)(p * 16 + (lane & 15)) * SQp + kf * 32 + (lane >> 4) * 16);
                uint32_t b0[2] = {k4[0], k4[2]}, b1[2] = {k4[1], k4[3]};
                mma_16816(sacc[2 * p],     qa[kf], b0);
                mma_16816(sacc[2 * p + 1], qa[kf], b1);
            }
        }

        if (kt == qt) {
            const int lr0 = w * 16 + (lane >> 2), lr1 = lr0 + 8;
#pragma unroll
            for (int nf = 0; nf < 16; nf++) {
                int lc = nf * 8 + (lane & 3) * 2;
                if (lc     > lr0) sacc[nf][0] = -1e30f;
                if (lc + 1 > lr0) sacc[nf][1] = -1e30f;
                if (lc     > lr1) sacc[nf][2] = -1e30f;
                if (lc + 1 > lr1) sacc[nf][3] = -1e30f;
            }
        }

        // ---- online softmax ----
        float tm0 = -1e30f, tm1 = -1e30f;
#pragma unroll
        for (int nf = 0; nf < 16; nf++) {
            tm0 = fmaxf(tm0, fmaxf(sacc[nf][0], sacc[nf][1]));
            tm1 = fmaxf(tm1, fmaxf(sacc[nf][2], sacc[nf][3]));
        }
        tm0 = fmaxf(tm0, __shfl_xor_sync(0xffffffffu, tm0, 1));
        tm0 = fmaxf(tm0, __shfl_xor_sync(0xffffffffu, tm0, 2));
        tm1 = fmaxf(tm1, __shfl_xor_sync(0xffffffffu, tm1, 1));
        tm1 = fmaxf(tm1, __shfl_xor_sync(0xffffffffu, tm1, 2));
        float nm0 = fmaxf(m0, tm0), nm1 = fmaxf(m1, tm1);
        float c0 = __expf(m0 - nm0), c1 = __expf(m1 - nm1);
        m0 = nm0; m1 = nm1;
        float ts0 = 0.f, ts1 = 0.f;
#pragma unroll
        for (int nf = 0; nf < 16; nf++) {
            sacc[nf][0] = __expf(sacc[nf][0] - nm0);
            sacc[nf][1] = __expf(sacc[nf][1] - nm0);
            sacc[nf][2] = __expf(sacc[nf][2] - nm1);
            sacc[nf][3] = __expf(sacc[nf][3] - nm1);
            ts0 += sacc[nf][0] + sacc[nf][1];
            ts1 += sacc[nf][2] + sacc[nf][3];
        }
        ts0 += __shfl_xor_sync(0xffffffffu, ts0, 1);
        ts0 += __shfl_xor_sync(0xffffffffu, ts0, 2);
        ts1 += __shfl_xor_sync(0xffffffffu, ts1, 1);
        ts1 += __shfl_xor_sync(0xffffffffu, ts1, 2);
        l0 = l0 * c0 + ts0;
        l1 = l1 * c1 + ts1;
#pragma unroll
        for (int nf = 0; nf < 12; nf++) {
            oacc[nf][0] *= c0; oacc[nf][1] *= c0;
            oacc[nf][2] *= c1; oacc[nf][3] *= c1;
        }

        // ---- O += P V   (V row-major [t][d], trans-ldmatrix B fragments) ----
#pragma unroll
        for (int t = 0; t < 8; t++) {
            uint32_t pa[4];
            pa[0] = pack2h(sacc[2 * t][0],     sacc[2 * t][1]);
            pa[1] = pack2h(sacc[2 * t][2],     sacc[2 * t][3]);
            pa[2] = pack2h(sacc[2 * t + 1][0], sacc[2 * t + 1][1]);
            pa[3] = pack2h(sacc[2 * t + 1][2], sacc[2 * t + 1][3]);
#pragma unroll
            for (int dg = 0; dg < 6; dg++) {
                uint32_t v4[4];
                ldsm_x4_trans(v4, Vb + (uint32_t)(t * 16 + (lane & 15)) * SQp
                                     + dg * 32 + (lane >> 4) * 16);
                uint32_t b0[2] = {v4[0], v4[1]}, b1[2] = {v4[2], v4[3]};
                mma_16816(oacc[2 * dg],     pa, b0);
                mma_16816(oacc[2 * dg + 1], pa, b1);
            }
        }

        if (kt < qt) {
            CP_WAIT0();
            __syncthreads();
        }
    }

    // ---- epilogue: normalize, write y fp16 [B*T, C] ----
    const float i0 = 1.f / l0, i1 = 1.f / l1;
    const size_t row0 = (size_t)b * Tn + qt * 128 + w * 16 + (lane >> 2);
#pragma unroll
    for (int nf = 0; nf < 12; nf++) {
        int col = h * Dn + nf * 8 + (lane & 3) * 2;
        *(uint32_t*)(g_y16 + row0 * Cn + col) =
            pack2h(oacc[nf][0] * i0, oacc[nf][1] * i0);
        *(uint32_t*)(g_y16 + (row0 + 8) * Cn + col) =
            pack2h(oacc[nf][2] * i1, oacc[nf][3] * i1);
    }
}

// ---------------------------------------------------------------------------
// Launch pipeline
// ---------------------------------------------------------------------------
extern "C" void kernel_launch(void* const* d_in, const int* in_sizes, int n_in,
                              void* d_out, int out_size)
{
    const float* x      = (const float*)d_in[0];
    const float* W_attn = (const float*)d_in[1];
    const float* b_attn = (const float*)d_in[2];
    const float* W_proj = (const float*)d_in[3];
    const float* b_proj = (const float*)d_in[4];
    float* out = (float*)d_out;

    __half *x16, *y16, *wat, *wpt;
    cudaGetSymbolAddress((void**)&x16, g_x16);
    cudaGetSymbolAddress((void**)&y16, g_y16);
    cudaGetSymbolAddress((void**)&wat, g_WaT);
    cudaGetSymbolAddress((void**)&wpt, g_WpT);

    cudaFuncSetAttribute(qkv_gemm,
                         cudaFuncAttributeMaxDynamicSharedMemorySize, QKV_SMEM);
    cudaFuncSetAttribute(proj_gemm,
                         cudaFuncAttributeMaxDynamicSharedMemorySize, PROJ_SMEM);
    cudaFuncSetAttribute(attention_mma,
                         cudaFuncAttributeMaxDynamicSharedMemorySize, ATT_SMEM);

    // 0) fused input prep (x convert + both weight transposes, one launch)
    prep_all<<<PREP_BLKS, 256>>>(x, W_attn, W_proj);

    // 1) fused qkv GEMM -> Q16/K16/V16 directly
    qkv_gemm<<<dim3(N3 / 256, Mn / 128), 256, QKV_SMEM>>>(x16, wat, b_attn);

    // 2) pipelined flash attention (tensor cores)
    attention_mma<<<dim3(Tn / 128, Bn * Hn), 256, ATT_SMEM>>>();

    // 3) out = y @ W_proj + b_proj   [8192, 768]  (2 CTAs/SM)
    proj_gemm<<<dim3(Cn / 128, Mn / 128), 256, PROJ_SMEM>>>(
        y16, wpt, b_proj, out);
}